// round 5
// baseline (speedup 1.0000x reference)
#include <cuda_runtime.h>
#include <cuda_bf16.h>
#include <math.h>
#include <string.h>
#include <stdint.h>

#define C 256
#define BATCH 8
#define NTOK 5376
#define TOT (BATCH*NTOK)   /* 43008 */
#define KINST 100
#define LN_EPS 1e-5f

#define NI_OFF 0
#define SC_OFF 8
#define CL_OFF 808
#define BX_OFF 1608

// ---------------- device scratch ----------------
__device__ __nv_bfloat16 g_flathi[TOT*C], g_flatlo[TOT*C];
__device__ float g_logits[TOT];
__device__ float g_vals[BATCH*KINST];
__device__ int   g_idx[BATCH*KINST];
__device__ __nv_bfloat16 g_hd[4][896*256];   // cls hi/lo, box hi/lo final planes
__device__ __nv_bfloat16 g_whi[12*65536];    // pre-swizzled head weights
__device__ __nv_bfloat16 g_wlo[12*65536];
__device__ __nv_bfloat16 g_lathi[458752];    // lateral weights [O,Cin]
__device__ __nv_bfloat16 g_latlo[458752];

// ---------------- helpers ----------------
__device__ __forceinline__ uint32_t smem_u32(const void* p){
    uint32_t a;
    asm("{ .reg .u64 t; cvta.to.shared.u64 t, %1; cvt.u32.u64 %0, t; }" : "=r"(a) : "l"(p));
    return a;
}
__device__ __forceinline__ uint32_t sw128(uint32_t o){ return o ^ ((o >> 3) & 0x70); }

__device__ __forceinline__ void ldsm4(uint32_t addr, uint32_t& r0, uint32_t& r1,
                                      uint32_t& r2, uint32_t& r3){
    asm volatile("ldmatrix.sync.aligned.m8n8.x4.shared.b16 {%0,%1,%2,%3}, [%4];"
                 : "=r"(r0), "=r"(r1), "=r"(r2), "=r"(r3) : "r"(addr));
}
__device__ __forceinline__ void mma_bf16(float* d, const uint32_t* a, uint32_t b0, uint32_t b1){
    asm volatile(
        "mma.sync.aligned.m16n8k16.row.col.f32.bf16.bf16.f32 "
        "{%0,%1,%2,%3}, {%4,%5,%6,%7}, {%8,%9}, {%0,%1,%2,%3};"
        : "+f"(d[0]), "+f"(d[1]), "+f"(d[2]), "+f"(d[3])
        : "r"(a[0]), "r"(a[1]), "r"(a[2]), "r"(a[3]), "r"(b0), "r"(b1));
}
__device__ __forceinline__ void cpasync16(uint32_t dst, const void* src){
    asm volatile("cp.async.cg.shared.global [%0], [%1], 16;" :: "r"(dst), "l"(src));
}
__device__ __forceinline__ void cp_commit(){
    asm volatile("cp.async.commit_group;" ::: "memory");
}
__device__ __forceinline__ void store_hl2(__nv_bfloat16* Yhi, __nv_bfloat16* Ylo,
                                          size_t row, int c0, float u0, float u1){
    __nv_bfloat16 h0=__float2bfloat16(u0), h1=__float2bfloat16(u1);
    __nv_bfloat16 l0=__float2bfloat16(u0-__bfloat162float(h0));
    __nv_bfloat16 l1=__float2bfloat16(u1-__bfloat162float(h1));
    __nv_bfloat162 hh; hh.x=h0; hh.y=h1;
    __nv_bfloat162 ll; ll.x=l0; ll.y=l1;
    *(__nv_bfloat162*)(Yhi+row*256+c0) = hh;
    *(__nv_bfloat162*)(Ylo+row*256+c0) = ll;
}

struct Acc { float v[4][8][4]; };

// half-N (128-col) compute sub-step: A chunk (128x64) x W half-chunk (128x64)
template<int H>
__device__ __forceinline__ void sub_compute(uint32_t ah_b, uint32_t al_b,
    uint32_t bh_b, uint32_t bl_b, int lane, int wm, int wn, Acc& acc)
{
    const int lm_r = (lane & 7) + ((lane >> 3) & 1) * 8;
    const int lm_k = (lane >> 4) * 16;
#pragma unroll
    for (int ks = 0; ks < 4; ks++) {
        const int kb = ks * 32 + lm_k;
        uint32_t ah[4][4], al[4][4];
#pragma unroll
        for (int mi = 0; mi < 4; mi++) {
            int row = wm * 64 + mi * 16 + lm_r;
            uint32_t so = sw128((uint32_t)(row * 128 + kb));
            ldsm4(ah_b + so, ah[mi][0], ah[mi][1], ah[mi][2], ah[mi][3]);
            ldsm4(al_b + so, al[mi][0], al[mi][1], al[mi][2], al[mi][3]);
        }
#pragma unroll
        for (int bi = 0; bi < 2; bi++) {
            int nr = wn * 32 + bi * 16 + lm_r;
            uint32_t so = sw128((uint32_t)(nr * 128 + kb));
            uint32_t bh0,bh1,bh2,bh3, bl0,bl1,bl2,bl3;
            ldsm4(bh_b + so, bh0,bh1,bh2,bh3);
            ldsm4(bl_b + so, bl0,bl1,bl2,bl3);
#pragma unroll
            for (int mi=0;mi<4;mi++) mma_bf16(acc.v[mi][H*4+2*bi],   ah[mi], bh0, bh2);
#pragma unroll
            for (int mi=0;mi<4;mi++) mma_bf16(acc.v[mi][H*4+2*bi+1], ah[mi], bh1, bh3);
#pragma unroll
            for (int mi=0;mi<4;mi++) mma_bf16(acc.v[mi][H*4+2*bi],   ah[mi], bl0, bl2);
#pragma unroll
            for (int mi=0;mi<4;mi++) mma_bf16(acc.v[mi][H*4+2*bi+1], ah[mi], bl1, bl3);
#pragma unroll
            for (int mi=0;mi<4;mi++) mma_bf16(acc.v[mi][H*4+2*bi],   al[mi], bh0, bh2);
#pragma unroll
            for (int mi=0;mi<4;mi++) mma_bf16(acc.v[mi][H*4+2*bi+1], al[mi], bh1, bh3);
        }
    }
}

// full-N (256-col) chunk, used by the lateral kernel
__device__ __forceinline__ void do_chunk_full(uint32_t ah_b, uint32_t al_b,
    uint32_t bh_b, uint32_t bl_b, int lane, int wm, int wn, Acc& acc)
{
    const int lm_r = (lane & 7) + ((lane >> 3) & 1) * 8;
    const int lm_k = (lane >> 4) * 16;
#pragma unroll
    for (int ks = 0; ks < 4; ks++) {
        const int kb = ks * 32 + lm_k;
        uint32_t ah[4][4], al[4][4];
#pragma unroll
        for (int mi = 0; mi < 4; mi++) {
            int row = wm * 64 + mi * 16 + lm_r;
            uint32_t so = sw128((uint32_t)(row * 128 + kb));
            ldsm4(ah_b + so, ah[mi][0], ah[mi][1], ah[mi][2], ah[mi][3]);
            ldsm4(al_b + so, al[mi][0], al[mi][1], al[mi][2], al[mi][3]);
        }
#pragma unroll
        for (int bi = 0; bi < 4; bi++) {
            int nr = wn * 64 + bi * 16 + lm_r;
            uint32_t so = sw128((uint32_t)(nr * 128 + kb));
            uint32_t bh0,bh1,bh2,bh3, bl0,bl1,bl2,bl3;
            ldsm4(bh_b + so, bh0,bh1,bh2,bh3);
            ldsm4(bl_b + so, bl0,bl1,bl2,bl3);
#pragma unroll
            for (int mi=0;mi<4;mi++) mma_bf16(acc.v[mi][2*bi],   ah[mi], bh0, bh2);
#pragma unroll
            for (int mi=0;mi<4;mi++) mma_bf16(acc.v[mi][2*bi+1], ah[mi], bh1, bh3);
#pragma unroll
            for (int mi=0;mi<4;mi++) mma_bf16(acc.v[mi][2*bi],   ah[mi], bl0, bl2);
#pragma unroll
            for (int mi=0;mi<4;mi++) mma_bf16(acc.v[mi][2*bi+1], ah[mi], bl1, bl3);
#pragma unroll
            for (int mi=0;mi<4;mi++) mma_bf16(acc.v[mi][2*bi],   al[mi], bh0, bh2);
#pragma unroll
            for (int mi=0;mi<4;mi++) mma_bf16(acc.v[mi][2*bi+1], al[mi], bh1, bh3);
        }
    }
}

// ================= fused 4-layer MLP kernel (A resident in smem) =============
#define F_AH   0
#define F_AL   65536
#define F_WB   131072     /* 2 bufs x (hi 16K + lo 16K) */
#define F_PB   196608     /* 4 x 256 f */
#define F_PG   200704
#define F_PO   204800
#define F_WF   208896
#define F_RS   209920
#define F_RQ   210432
#define F_RD   210944
#define F_SIDX 211456
#define F_SMEM 211968

struct FArgs {
    const __nv_bfloat16 *Ahi, *Alo;
    const __nv_bfloat16 *whi, *wlo;
    const float *pb, *pg, *po;
    const float *pb2, *pg2, *po2;
    const float *wf, *wfb;
    float* logits;
    __nv_bfloat16 *Yhi, *Ylo, *Y2hi, *Y2lo;
    const int* idx;
    int mat0, mat0b, nrows, split, gather;
};

__global__ __launch_bounds__(256) void fused_mlp(FArgs a)
{
    extern __shared__ char smem[];
    const uint32_t sb = smem_u32(smem);
    const int tid = threadIdx.x, lane = tid & 31, wid = tid >> 5;
    const int wm = wid >> 2, wn = wid & 3;

    int blk = blockIdx.x;
    const float *pb = a.pb, *pg = a.pg, *po = a.po;
    __nv_bfloat16 *Yhi = a.Yhi, *Ylo = a.Ylo;
    int mat0 = a.mat0;
    if (blk >= a.split) {
        blk -= a.split;
        pb = a.pb2; pg = a.pg2; po = a.po2; mat0 = a.mat0b;
        Yhi = a.Y2hi; Ylo = a.Y2lo;
    }
    const int row0 = blk * 128;

#pragma unroll
    for (int l = 0; l < 4; l++) {
        ((float*)(smem+F_PB))[l*256+tid] = pb[l*256+tid];
        ((float*)(smem+F_PG))[l*256+tid] = pg[l*256+tid];
        ((float*)(smem+F_PO))[l*256+tid] = po[l*256+tid];
    }
    if (a.wf) ((float*)(smem+F_WF))[tid] = a.wf[tid];
    if (tid < 128) {
        ((float*)(smem+F_RS))[tid] = 0.f;
        ((float*)(smem+F_RQ))[tid] = 0.f;
        ((float*)(smem+F_RD))[tid] = 0.f;
        int i = row0 + tid; if (i >= a.nrows) i = a.nrows - 1;
        int gl = a.gather ? (i / KINST) * NTOK + a.idx[i] : i;
        ((int*)(smem+F_SIDX))[tid] = gl;
    }
    __syncthreads();
    const int* sidx = (const int*)(smem + F_SIDX);

    auto issueA = [&](int c){
#pragma unroll
        for (int j = 0; j < 4; j++) {
            int u = tid + j * 256;
            int r = u >> 3, s = u & 7;
            size_t off = (size_t)sidx[r] * 256 + c * 64 + s * 8;
            uint32_t d = sw128((uint32_t)(r * 128 + s * 16)) + (uint32_t)(c * 16384);
            cpasync16(sb + F_AH + d, a.Ahi + off);
            cpasync16(sb + F_AL + d, a.Alo + off);
        }
    };
    auto issueW = [&](int s){
        int l = s >> 3, t = s & 7, buf = s & 1;
        const __nv_bfloat16* wh = a.whi + (size_t)(mat0 + l) * 65536 + (size_t)t * 8192;
        const __nv_bfloat16* wl = a.wlo + (size_t)(mat0 + l) * 65536 + (size_t)t * 8192;
        uint32_t dst = sb + F_WB + buf * 32768;
#pragma unroll
        for (int j = 0; j < 4; j++) {
            int u = tid + j * 256;
            cpasync16(dst + u * 16,         wh + u * 8);
            cpasync16(dst + 16384 + u * 16, wl + u * 8);
        }
    };

    issueA(0); issueW(0); cp_commit();
    issueW(1); cp_commit();

    Acc acc;
#pragma unroll
    for (int mi = 0; mi < 4; mi++)
#pragma unroll
        for (int ni = 0; ni < 8; ni++)
#pragma unroll
            for (int q = 0; q < 4; q++) acc.v[mi][ni][q] = 0.f;

    const float* f_g_all  = (float*)(smem + F_PG);
    const float* f_b_all  = (float*)(smem + F_PB);
    const float* f_o_all  = (float*)(smem + F_PO);
    const float* f_wf = (float*)(smem + F_WF);
    float* rowsum = (float*)(smem + F_RS);
    float* rowsq  = (float*)(smem + F_RQ);
    float* rowdot = (float*)(smem + F_RD);
    const int rloc = lane >> 2;

    for (int s = 0; s < 32; s++) {
        asm volatile("cp.async.wait_group 1;" ::: "memory");
        __syncthreads();
        const int t = s & 7, kc = t >> 1, h = t & 1, buf = s & 1;
        uint32_t ab = sb + F_AH + kc * 16384;
        uint32_t al = sb + F_AL + kc * 16384;
        uint32_t bh = sb + F_WB + buf * 32768;
        uint32_t bl = bh + 16384;
        if (h == 0) sub_compute<0>(ab, al, bh, bl, lane, wm, wn, acc);
        else        sub_compute<1>(ab, al, bh, bl, lane, wm, wn, acc);
        __syncthreads();
        int nx = s + 2;
        if (nx < 32) {
            issueW(nx);
            if (nx < 8 && (nx & 1) == 0) issueA(nx >> 1);
        }
        cp_commit();

        if (t == 7) {
            // =============== layer epilogue ===============
            const int l = s >> 3;
            const float* f_bias = f_b_all + l * 256;
            const float* f_g    = f_g_all + l * 256;
            const float* f_o    = f_o_all + l * 256;
            // phase 1: bias + row stats
#pragma unroll
            for (int mi = 0; mi < 4; mi++) {
                float sA=0.f, qA=0.f, sB=0.f, qB=0.f;
#pragma unroll
                for (int ni = 0; ni < 8; ni++) {
                    int c0 = (ni>>2)*128 + wn*32 + ((ni>>1)&1)*16 + (ni&1)*8 + (lane&3)*2;
                    float b0 = f_bias[c0], b1 = f_bias[c0+1];
                    float v0 = acc.v[mi][ni][0] + b0;
                    float v1 = acc.v[mi][ni][1] + b1;
                    float v2 = acc.v[mi][ni][2] + b0;
                    float v3 = acc.v[mi][ni][3] + b1;
                    acc.v[mi][ni][0]=v0; acc.v[mi][ni][1]=v1;
                    acc.v[mi][ni][2]=v2; acc.v[mi][ni][3]=v3;
                    sA += v0 + v1; qA += v0*v0 + v1*v1;
                    sB += v2 + v3; qB += v2*v2 + v3*v3;
                }
#pragma unroll
                for (int o = 1; o <= 2; o <<= 1) {
                    sA += __shfl_xor_sync(0xffffffffu, sA, o);
                    qA += __shfl_xor_sync(0xffffffffu, qA, o);
                    sB += __shfl_xor_sync(0xffffffffu, sB, o);
                    qB += __shfl_xor_sync(0xffffffffu, qB, o);
                }
                if ((lane & 3) == 0) {
                    int rA = wm * 64 + mi * 16 + rloc;
                    atomicAdd(&rowsum[rA], sA);   atomicAdd(&rowsq[rA], qA);
                    atomicAdd(&rowsum[rA+8], sB); atomicAdd(&rowsq[rA+8], qB);
                }
            }
            __syncthreads();
            // phase 2
            if (a.wf && l == 3) {
                // fused loc final: LN -> SiLU -> dot(Wf) -> logits
#pragma unroll
                for (int mi = 0; mi < 4; mi++) {
                    int rA = wm * 64 + mi * 16 + rloc;
                    int rB = rA + 8;
                    float mA = rowsum[rA] * (1.f/256.f);
                    float rsA = rsqrtf(rowsq[rA] * (1.f/256.f) - mA*mA + LN_EPS);
                    float mB = rowsum[rB] * (1.f/256.f);
                    float rsB = rsqrtf(rowsq[rB] * (1.f/256.f) - mB*mB + LN_EPS);
                    float pA = 0.f, pB = 0.f;
#pragma unroll
                    for (int ni = 0; ni < 8; ni++) {
                        int c0 = (ni>>2)*128 + wn*32 + ((ni>>1)&1)*16 + (ni&1)*8 + (lane&3)*2;
                        float g0=f_g[c0], g1=f_g[c0+1], o0=f_o[c0], o1=f_o[c0+1];
                        float u0 = (acc.v[mi][ni][0]-mA)*rsA*g0 + o0;
                        float u1 = (acc.v[mi][ni][1]-mA)*rsA*g1 + o1;
                        float u2 = (acc.v[mi][ni][2]-mB)*rsB*g0 + o0;
                        float u3 = (acc.v[mi][ni][3]-mB)*rsB*g1 + o1;
                        u0 = u0/(1.f+expf(-u0)); u1 = u1/(1.f+expf(-u1));
                        u2 = u2/(1.f+expf(-u2)); u3 = u3/(1.f+expf(-u3));
                        pA += u0*f_wf[c0] + u1*f_wf[c0+1];
                        pB += u2*f_wf[c0] + u3*f_wf[c0+1];
                    }
#pragma unroll
                    for (int o = 1; o <= 2; o <<= 1) {
                        pA += __shfl_xor_sync(0xffffffffu, pA, o);
                        pB += __shfl_xor_sync(0xffffffffu, pB, o);
                    }
                    if ((lane & 3) == 0) {
                        atomicAdd(&rowdot[rA], pA);
                        atomicAdd(&rowdot[rB], pB);
                    }
                }
                __syncthreads();
                if (tid < 128) {
                    int rg = row0 + tid;
                    if (rg < a.nrows) a.logits[rg] = rowdot[tid] + a.wfb[0];
                }
            } else {
#pragma unroll
                for (int mi = 0; mi < 4; mi++) {
                    int rA = wm * 64 + mi * 16 + rloc;
                    int rB = rA + 8;
                    float mA = rowsum[rA] * (1.f/256.f);
                    float rsA = rsqrtf(rowsq[rA] * (1.f/256.f) - mA*mA + LN_EPS);
                    float mB = rowsum[rB] * (1.f/256.f);
                    float rsB = rsqrtf(rowsq[rB] * (1.f/256.f) - mB*mB + LN_EPS);
#pragma unroll
                    for (int ni = 0; ni < 8; ni++) {
                        int c0 = (ni>>2)*128 + wn*32 + ((ni>>1)&1)*16 + (ni&1)*8 + (lane&3)*2;
                        float g0=f_g[c0], g1=f_g[c0+1], o0=f_o[c0], o1=f_o[c0+1];
                        float u0 = (acc.v[mi][ni][0]-mA)*rsA*g0 + o0;
                        float u1 = (acc.v[mi][ni][1]-mA)*rsA*g1 + o1;
                        float u2 = (acc.v[mi][ni][2]-mB)*rsB*g0 + o0;
                        float u3 = (acc.v[mi][ni][3]-mB)*rsB*g1 + o1;
                        u0 = u0/(1.f+expf(-u0)); u1 = u1/(1.f+expf(-u1));
                        u2 = u2/(1.f+expf(-u2)); u3 = u3/(1.f+expf(-u3));
                        if (l == 3) {
                            // head final -> gmem planes
                            store_hl2(Yhi, Ylo, (size_t)(row0 + rA), c0, u0, u1);
                            store_hl2(Yhi, Ylo, (size_t)(row0 + rB), c0, u2, u3);
                        } else {
                            // write back into resident A smem (hi/lo, swizzled)
                            __nv_bfloat16 h0=__float2bfloat16(u0), h1=__float2bfloat16(u1);
                            __nv_bfloat16 l0=__float2bfloat16(u0-__bfloat162float(h0));
                            __nv_bfloat16 l1=__float2bfloat16(u1-__bfloat162float(h1));
                            __nv_bfloat16 h2=__float2bfloat16(u2), h3=__float2bfloat16(u3);
                            __nv_bfloat16 l2=__float2bfloat16(u2-__bfloat162float(h2));
                            __nv_bfloat16 l3=__float2bfloat16(u3-__bfloat162float(h3));
                            int kcc = c0 >> 6;
                            uint32_t offA = (uint32_t)(kcc*16384) + sw128((uint32_t)(rA*128 + (c0&63)*2));
                            uint32_t offB = (uint32_t)(kcc*16384) + sw128((uint32_t)(rB*128 + (c0&63)*2));
                            __nv_bfloat162 hh; __nv_bfloat162 ll;
                            hh.x=h0; hh.y=h1; ll.x=l0; ll.y=l1;
                            *(__nv_bfloat162*)(smem + F_AH + offA) = hh;
                            *(__nv_bfloat162*)(smem + F_AL + offA) = ll;
                            hh.x=h2; hh.y=h3; ll.x=l2; ll.y=l3;
                            *(__nv_bfloat162*)(smem + F_AH + offB) = hh;
                            *(__nv_bfloat162*)(smem + F_AL + offB) = ll;
                        }
                    }
                }
            }
            __syncthreads();
            if (tid < 128 && l < 3) { rowsum[tid] = 0.f; rowsq[tid] = 0.f; }
            if (l < 3) {
#pragma unroll
                for (int mi = 0; mi < 4; mi++)
#pragma unroll
                    for (int ni = 0; ni < 8; ni++)
#pragma unroll
                        for (int q = 0; q < 4; q++) acc.v[mi][ni][q] = 0.f;
            }
        }
    }
}

// ================= lateral conv + BN kernel ==================================
#define L_AH 0
#define L_AL 16384
#define L_BH 32768
#define L_BL 65536
#define L_PG 98304
#define L_PO 99328
#define L_SMEM 100352

struct LArgs {
    const float* Xf;
    const __nv_bfloat16 *Whi, *Wlo;
    const float *pg, *po, *pm, *pv;
    __nv_bfloat16 *Yhi, *Ylo;
    int Kdim, HW, lvl_off;
};

__global__ __launch_bounds__(256) void lat_gemm(LArgs a)
{
    extern __shared__ char smem[];
    const uint32_t sb = smem_u32(smem);
    const int tid = threadIdx.x, lane = tid & 31, wid = tid >> 5;
    const int wm = wid >> 2, wn = wid & 3;
    const int row0 = blockIdx.x * 128;
    const int bb = row0 / a.HW, hw0 = row0 % a.HW;

    {
        float sc = a.pg[tid] * rsqrtf(a.pv[tid] + LN_EPS);
        ((float*)(smem+L_PG))[tid] = sc;
        ((float*)(smem+L_PO))[tid] = a.po[tid] - a.pm[tid] * sc;
    }
    __syncthreads();

    Acc acc;
#pragma unroll
    for (int mi = 0; mi < 4; mi++)
#pragma unroll
        for (int ni = 0; ni < 8; ni++)
#pragma unroll
            for (int q = 0; q < 4; q++) acc.v[mi][ni][q] = 0.f;

    const int nch = a.Kdim >> 6;
    for (int kc = 0; kc < nch; kc++) {
        const int k0 = kc * 64;
        // W chunk (256 outs x 64 k) via cp.async with on-the-fly swizzle
#pragma unroll
        for (int j = 0; j < 8; j++) {
            int f = tid + j * 256;
            int o = f >> 3, s = f & 7;
            size_t off = (size_t)o * a.Kdim + k0 + s * 8;
            uint32_t d = sw128((uint32_t)(o * 128 + s * 16));
            cpasync16(sb + L_BH + d, a.Whi + off);
            cpasync16(sb + L_BL + d, a.Wlo + off);
        }
        cp_commit();
        // A convert (fp32 [Cin,HW] -> bf16 hi/lo tile), overlaps with W loads
#pragma unroll
        for (int j = 0; j < 8; j++) {
            int f = tid + j * 256;
            int kk = f >> 5, r4 = (f & 31) * 4;
            float4 v = *(const float4*)(a.Xf + ((size_t)(bb * a.Kdim + k0 + kk)) * a.HW + hw0 + r4);
            float xs[4] = { v.x, v.y, v.z, v.w };
#pragma unroll
            for (int t = 0; t < 4; t++) {
                __nv_bfloat16 h = __float2bfloat16(xs[t]);
                __nv_bfloat16 l = __float2bfloat16(xs[t] - __bfloat162float(h));
                uint32_t so = sw128((uint32_t)((r4 + t) * 128 + kk * 2));
                *(unsigned short*)(smem + L_AH + so) = __bfloat16_as_ushort(h);
                *(unsigned short*)(smem + L_AL + so) = __bfloat16_as_ushort(l);
            }
        }
        asm volatile("cp.async.wait_group 0;" ::: "memory");
        __syncthreads();
        do_chunk_full(sb + L_AH, sb + L_AL, sb + L_BH, sb + L_BL, lane, wm, wn, acc);
        __syncthreads();
    }

    const float* f_g = (float*)(smem + L_PG);
    const float* f_o = (float*)(smem + L_PO);
    const int rloc = lane >> 2;
#pragma unroll
    for (int mi = 0; mi < 4; mi++) {
        int rA = wm * 64 + mi * 16 + rloc;
        int rB = rA + 8;
        size_t oA = (size_t)bb * NTOK + a.lvl_off + hw0 + rA;
        size_t oB = oA + 8;
#pragma unroll
        for (int ni = 0; ni < 8; ni++) {
            int c0 = wn * 64 + ni * 8 + (lane & 3) * 2;
            float g0 = f_g[c0], g1 = f_g[c0+1], o0 = f_o[c0], o1 = f_o[c0+1];
            store_hl2(a.Yhi, a.Ylo, oA, c0, acc.v[mi][ni][0]*g0+o0, acc.v[mi][ni][1]*g1+o1);
            store_hl2(a.Yhi, a.Ylo, oB, c0, acc.v[mi][ni][2]*g0+o0, acc.v[mi][ni][3]*g1+o1);
        }
    }
}

// ---------------- weight prep: head mats [K,O] -> swizzled bf16 hi/lo --------
__global__ __launch_bounds__(256) void prep_tr_sw(
    const float* __restrict__ locw, const float* __restrict__ clsw,
    const float* __restrict__ boxw, __nv_bfloat16* __restrict__ hi,
    __nv_bfloat16* __restrict__ lo)
{
    int mat = blockIdx.x >> 8;
    int o   = blockIdx.x & 255;
    int k   = threadIdx.x;
    const float* W = (mat < 4 ? locw : (mat < 8 ? clsw : boxw)) + (size_t)(mat & 3) * 65536;
    float v = W[k * 256 + o];
    __nv_bfloat16 h = __float2bfloat16(v);
    int half = o >> 7, ol = o & 127, kc = k >> 6, kl = k & 63;
    size_t oi = (size_t)mat * 65536 + (size_t)(kc * 2 + half) * 8192
              + (sw128((uint32_t)(ol * 128 + kl * 2)) >> 1);
    hi[oi] = h;
    lo[oi] = __float2bfloat16(v - __bfloat162float(h));
}

__global__ __launch_bounds__(256) void prep_direct(
    const float* __restrict__ W, __nv_bfloat16* __restrict__ hi,
    __nv_bfloat16* __restrict__ lo, int n)
{
    int i = blockIdx.x * 256 + threadIdx.x;
    if (i < n) {
        float v = W[i];
        __nv_bfloat16 h = __float2bfloat16(v);
        hi[i] = h;
        lo[i] = __float2bfloat16(v - __bfloat162float(h));
    }
}

// ---------------- top-k ----------------
__global__ __launch_bounds__(512) void topk_kernel(
    const float* __restrict__ logits, float* __restrict__ vals, int* __restrict__ idxs)
{
    __shared__ float sv[NTOK];
    __shared__ float rv[16];
    __shared__ int   ri[16];
    const int b = blockIdx.x, tid = threadIdx.x;
    for (int i = tid; i < NTOK; i += 512) sv[i] = logits[b * NTOK + i];
    __syncthreads();
    for (int k = 0; k < KINST; k++) {
        float bv = -3.0e38f; int bi = 0;
        for (int i = tid; i < NTOK; i += 512) {
            float v = sv[i];
            if (v > bv) { bv = v; bi = i; }
        }
#pragma unroll
        for (int o = 16; o > 0; o >>= 1) {
            float ov = __shfl_xor_sync(0xffffffffu, bv, o);
            int   oi = __shfl_xor_sync(0xffffffffu, bi, o);
            if (ov > bv || (ov == bv && oi < bi)) { bv = ov; bi = oi; }
        }
        if ((tid & 31) == 0) { rv[tid >> 5] = bv; ri[tid >> 5] = bi; }
        __syncthreads();
        if (tid == 0) {
            for (int w = 1; w < 16; w++)
                if (rv[w] > bv || (rv[w] == bv && ri[w] < bi)) { bv = rv[w]; bi = ri[w]; }
            vals[b * KINST + k] = bv;
            idxs[b * KINST + k] = bi;
            sv[bi] = -3.3e38f;
        }
        __syncthreads();
    }
}

__device__ __forceinline__ float read_dim(const int* p) {
    int v = p[0];
    if (v > 0 && v < 1000000) return (float)v;
    return __int_as_float(v);
}

// ---------------- merged finals: cls argmax + box decode ----------------
__global__ __launch_bounds__(128) void finals_kernel(
    const __nv_bfloat16* __restrict__ chi, const __nv_bfloat16* __restrict__ clo,
    const __nv_bfloat16* __restrict__ bhi, const __nv_bfloat16* __restrict__ blo,
    const float* __restrict__ clsWf, const float* __restrict__ clsbf,
    const float* __restrict__ boxWf, const float* __restrict__ boxbf,
    const int* __restrict__ idxs, const int* __restrict__ p_fh,
    const int* __restrict__ p_fw, float* __restrict__ out)
{
    __shared__ float xc[256], xb[256], sval[80], e[4];
    int i = blockIdx.x, tid = threadIdx.x, lane = tid & 31, w = tid >> 5;
    {
        size_t base = (size_t)i * 256;
        xc[tid]     = __bfloat162float(chi[base+tid])     + __bfloat162float(clo[base+tid]);
        xc[tid+128] = __bfloat162float(chi[base+tid+128]) + __bfloat162float(clo[base+tid+128]);
        xb[tid]     = __bfloat162float(bhi[base+tid])     + __bfloat162float(blo[base+tid]);
        xb[tid+128] = __bfloat162float(bhi[base+tid+128]) + __bfloat162float(blo[base+tid+128]);
    }
    __syncthreads();
    float s = 0.f;
#pragma unroll
    for (int j = 0; j < 8; j++) {
        int k = lane + j * 32;
        s = fmaf(xb[k], boxWf[k * 4 + w], s);
    }
#pragma unroll
    for (int o = 16; o > 0; o >>= 1) s += __shfl_xor_sync(0xffffffffu, s, o);
    if (lane == 0) e[w] = expf(s + boxbf[w]);
    if (tid < 80) {
        float s2 = clsbf[tid];
        for (int k = 0; k < 256; k++) s2 = fmaf(xc[k], clsWf[k * 80 + tid], s2);
        sval[tid] = s2;
    }
    __syncthreads();
    if (tid == 0) {
        float bv = sval[0]; int bi = 0;
        for (int t = 1; t < 80; t++) if (sval[t] > bv) { bv = sval[t]; bi = t; }
        out[CL_OFF + i] = (float)bi;

        int n = idxs[i];
        int hsz, m;
        if (n < 4096)      { hsz = 64; m = n; }
        else if (n < 5120) { hsz = 32; m = n - 4096; }
        else               { hsz = 16; m = n - 5120; }
        int gy = m / hsz, gx = m % hsz;
        float inv = 1.0f / (float)hsz;
        float ox = (gx + 0.5f) * inv, oy = (gy + 0.5f) * inv;
        float half = 0.5f * inv;
        float fw = read_dim(p_fw), fh = read_dim(p_fh);
        float* o4 = out + BX_OFF + (size_t)i * 4;
        o4[0] = (ox - half * e[0]) * fw;
        o4[1] = (oy - half * e[1]) * fh;
        o4[2] = (ox + half * e[2]) * fw;
        o4[3] = (oy + half * e[3]) * fh;
    }
}

// ---------------- scores + num_instances ----------------
__global__ __launch_bounds__(800) void scores_kernel(
    const float* __restrict__ vals, float* __restrict__ out)
{
    __shared__ int cnt[BATCH];
    int tid = threadIdx.x;
    if (tid < BATCH) cnt[tid] = 0;
    __syncthreads();
    float v = vals[tid];
    out[SC_OFF + tid] = 1.f / (1.f + expf(-v));
    if (v > 0.f) atomicAdd(&cnt[tid / KINST], 1);
    __syncthreads();
    if (tid < BATCH) out[NI_OFF + tid] = (float)cnt[tid];
}

// ---------------- host launcher ----------------
extern "C" void kernel_launch(void* const* d_in, const int* in_sizes, int n_in,
                              void* d_out, int out_size)
{
    const float* x3     = (const float*)d_in[0];
    const float* x4     = (const float*)d_in[1];
    const float* x5     = (const float*)d_in[2];
    const float* lat_w3 = (const float*)d_in[3];
    const float* lat_w4 = (const float*)d_in[4];
    const float* lat_w5 = (const float*)d_in[5];
    const float* bn_g   = (const float*)d_in[6];
    const float* bn_b   = (const float*)d_in[7];
    const float* bn_m   = (const float*)d_in[8];
    const float* bn_v   = (const float*)d_in[9];
    const float* loc_Ws = (const float*)d_in[10];
    const float* loc_bs = (const float*)d_in[11];
    const float* loc_lng= (const float*)d_in[12];
    const float* loc_lnb= (const float*)d_in[13];
    const float* loc_Wf = (const float*)d_in[14];
    const float* loc_bf = (const float*)d_in[15];
    const float* cls_Ws = (const float*)d_in[16];
    const float* cls_bs = (const float*)d_in[17];
    const float* cls_lng= (const float*)d_in[18];
    const float* cls_lnb= (const float*)d_in[19];
    const float* cls_Wf = (const float*)d_in[20];
    const float* cls_bf = (const float*)d_in[21];
    const float* box_Ws = (const float*)d_in[22];
    const float* box_bs = (const float*)d_in[23];
    const float* box_lng= (const float*)d_in[24];
    const float* box_lnb= (const float*)d_in[25];
    const float* box_Wf = (const float*)d_in[26];
    const float* box_bf = (const float*)d_in[27];
    const int*   p_fh   = (const int*)d_in[28];
    const int*   p_fw   = (const int*)d_in[29];
    float* out = (float*)d_out;

    __nv_bfloat16 *flathi, *flatlo, *hd, *whi, *wlo, *lathi, *latlo;
    float *logits, *vals; int* idxp;
    cudaGetSymbolAddress((void**)&flathi, g_flathi);
    cudaGetSymbolAddress((void**)&flatlo, g_flatlo);
    cudaGetSymbolAddress((void**)&logits, g_logits);
    cudaGetSymbolAddress((void**)&vals,   g_vals);
    cudaGetSymbolAddress((void**)&idxp,   g_idx);
    cudaGetSymbolAddress((void**)&hd,     g_hd);
    cudaGetSymbolAddress((void**)&whi,    g_whi);
    cudaGetSymbolAddress((void**)&wlo,    g_wlo);
    cudaGetSymbolAddress((void**)&lathi,  g_lathi);
    cudaGetSymbolAddress((void**)&latlo,  g_latlo);

    const size_t HP = 896 * 256;
    __nv_bfloat16* c_hi = hd + 0*HP; __nv_bfloat16* c_lo = hd + 1*HP;
    __nv_bfloat16* b_hi = hd + 2*HP; __nv_bfloat16* b_lo = hd + 3*HP;

    cudaFuncSetAttribute(fused_mlp, cudaFuncAttributeMaxDynamicSharedMemorySize, F_SMEM);
    cudaFuncSetAttribute(lat_gemm,  cudaFuncAttributeMaxDynamicSharedMemorySize, L_SMEM);

    // 0) weight prep
    prep_tr_sw<<<12*256, 256>>>(loc_Ws, cls_Ws, box_Ws, whi, wlo);
    prep_direct<<<(65536+255)/256, 256>>>(lat_w3, lathi, latlo, 65536);
    prep_direct<<<(131072+255)/256, 256>>>(lat_w4, lathi + 65536, latlo + 65536, 131072);
    prep_direct<<<(262144+255)/256, 256>>>(lat_w5, lathi + 196608, latlo + 196608, 262144);

    // 1) laterals -> flat planes
    {
        LArgs L;
        L.Xf = x3; L.Whi = lathi; L.Wlo = latlo; L.Kdim = 256; L.HW = 4096; L.lvl_off = 0;
        L.pg = bn_g + 0*C; L.po = bn_b + 0*C; L.pm = bn_m + 0*C; L.pv = bn_v + 0*C;
        L.Yhi = flathi; L.Ylo = flatlo;
        lat_gemm<<<BATCH*4096/128, 256, L_SMEM>>>(L);
        L.Xf = x4; L.Whi = lathi + 65536; L.Wlo = latlo + 65536; L.Kdim = 512; L.HW = 1024; L.lvl_off = 4096;
        L.pg = bn_g + 1*C; L.po = bn_b + 1*C; L.pm = bn_m + 1*C; L.pv = bn_v + 1*C;
        lat_gemm<<<BATCH*1024/128, 256, L_SMEM>>>(L);
        L.Xf = x5; L.Whi = lathi + 196608; L.Wlo = latlo + 196608; L.Kdim = 1024; L.HW = 256; L.lvl_off = 5120;
        L.pg = bn_g + 2*C; L.po = bn_b + 2*C; L.pm = bn_m + 2*C; L.pv = bn_v + 2*C;
        lat_gemm<<<BATCH*256/128, 256, L_SMEM>>>(L);
    }

    // 2) fused loc MLP (4 layers + final dot) -> logits
    {
        FArgs F; memset(&F, 0, sizeof(F));
        F.Ahi = flathi; F.Alo = flatlo;
        F.whi = whi; F.wlo = wlo;
        F.mat0 = 0; F.mat0b = 0;
        F.pb = loc_bs; F.pg = loc_lng; F.po = loc_lnb;
        F.wf = loc_Wf; F.wfb = loc_bf; F.logits = logits;
        F.idx = idxp; F.nrows = TOT; F.split = 1 << 30; F.gather = 0;
        fused_mlp<<<TOT/128, 256, F_SMEM>>>(F);
    }

    // 3) top-k
    topk_kernel<<<BATCH, 512>>>(logits, vals, idxp);

    // 4) fused heads (cls split 0..6, box split 7..13), gather + 4 layers
    {
        FArgs H; memset(&H, 0, sizeof(H));
        H.Ahi = flathi; H.Alo = flatlo;
        H.whi = whi; H.wlo = wlo;
        H.mat0 = 4; H.mat0b = 8;
        H.pb = cls_bs; H.pg = cls_lng; H.po = cls_lnb;
        H.pb2 = box_bs; H.pg2 = box_lng; H.po2 = box_lnb;
        H.Yhi = c_hi; H.Ylo = c_lo; H.Y2hi = b_hi; H.Y2lo = b_lo;
        H.idx = idxp; H.nrows = 800; H.split = 7; H.gather = 1;
        fused_mlp<<<14, 256, F_SMEM>>>(H);
    }

    // 5) finals + scores
    finals_kernel<<<800, 128>>>(c_hi, c_lo, b_hi, b_lo,
        cls_Wf, cls_bf, box_Wf, box_bf, idxp, p_fh, p_fw, out);
    scores_kernel<<<1, 800>>>(vals, out);
}

// round 6
// speedup vs baseline: 1.6524x; 1.6524x over previous
#include <cuda_runtime.h>
#include <cuda_bf16.h>
#include <math.h>
#include <string.h>
#include <stdint.h>

#define C 256
#define BATCH 8
#define NTOK 5376
#define TOT (BATCH*NTOK)   /* 43008 */
#define KINST 100
#define LN_EPS 1e-5f

#define NI_OFF 0
#define SC_OFF 8
#define CL_OFF 808
#define BX_OFF 1608

// ---------------- device scratch ----------------
__device__ __nv_bfloat16 g_flathi[TOT*C], g_flatlo[TOT*C];
__device__ __nv_bfloat16 g_p0hi[TOT*C],  g_p0lo[TOT*C];
__device__ __nv_bfloat16 g_p1hi[TOT*C],  g_p1lo[TOT*C];
__device__ float g_logits[TOT];
__device__ float g_vals[BATCH*KINST];
__device__ int   g_idx[BATCH*KINST];
__device__ __nv_bfloat16 g_hd[8][896*256];   // head ping-pong planes
__device__ __nv_bfloat16 g_whi[12*65536];
__device__ __nv_bfloat16 g_wlo[12*65536];
__device__ __nv_bfloat16 g_lathi[458752];
__device__ __nv_bfloat16 g_latlo[458752];

// ---------------- helpers ----------------
__device__ __forceinline__ uint32_t smem_u32(const void* p){
    uint32_t a;
    asm("{ .reg .u64 t; cvta.to.shared.u64 t, %1; cvt.u32.u64 %0, t; }" : "=r"(a) : "l"(p));
    return a;
}
__device__ __forceinline__ uint32_t sw128(uint32_t o){ return o ^ ((o >> 3) & 0x70); }

__device__ __forceinline__ void ldsm4(uint32_t addr, uint32_t& r0, uint32_t& r1,
                                      uint32_t& r2, uint32_t& r3){
    asm volatile("ldmatrix.sync.aligned.m8n8.x4.shared.b16 {%0,%1,%2,%3}, [%4];"
                 : "=r"(r0), "=r"(r1), "=r"(r2), "=r"(r3) : "r"(addr));
}
__device__ __forceinline__ void mma_bf16(float* d, const uint32_t* a, uint32_t b0, uint32_t b1){
    asm volatile(
        "mma.sync.aligned.m16n8k16.row.col.f32.bf16.bf16.f32 "
        "{%0,%1,%2,%3}, {%4,%5,%6,%7}, {%8,%9}, {%0,%1,%2,%3};"
        : "+f"(d[0]), "+f"(d[1]), "+f"(d[2]), "+f"(d[3])
        : "r"(a[0]), "r"(a[1]), "r"(a[2]), "r"(a[3]), "r"(b0), "r"(b1));
}
__device__ __forceinline__ void cpasync16(uint32_t dst, const void* src){
    asm volatile("cp.async.cg.shared.global [%0], [%1], 16;" :: "r"(dst), "l"(src));
}
__device__ __forceinline__ void cp_commit(){
    asm volatile("cp.async.commit_group;" ::: "memory");
}
__device__ __forceinline__ void store_hl2(__nv_bfloat16* Yhi, __nv_bfloat16* Ylo,
                                          size_t row, int c0, float u0, float u1){
    __nv_bfloat16 h0=__float2bfloat16(u0), h1=__float2bfloat16(u1);
    __nv_bfloat16 l0=__float2bfloat16(u0-__bfloat162float(h0));
    __nv_bfloat16 l1=__float2bfloat16(u1-__bfloat162float(h1));
    __nv_bfloat162 hh; hh.x=h0; hh.y=h1;
    __nv_bfloat162 ll; ll.x=l0; ll.y=l1;
    *(__nv_bfloat162*)(Yhi+row*256+c0) = hh;
    *(__nv_bfloat162*)(Ylo+row*256+c0) = ll;
}

// ---------------- smem layout (bytes) ----------------
#define STAGE   98304
#define AH_OFF  0
#define AL_OFF  16384
#define BH_OFF  32768
#define BL_OFF  65536
#define P_PB    196608
#define P_PG    197632
#define P_PO    198656
#define P_WF    199680
#define P_RS    200704
#define P_RQ    201216
#define P_RD    201728
#define P_SIDX  202240
#define SMEM_TOTAL 202752

struct GArgs {
    const __nv_bfloat16 *Ahi, *Alo, *A2hi, *A2lo;
    const float* Xf;
    const __nv_bfloat16 *Whi, *Wlo, *W2hi, *W2lo;
    const float *pb, *pg, *po, *pm, *pv;
    const float *pb2, *pg2, *po2;
    __nv_bfloat16 *Yhi, *Ylo, *Y2hi, *Y2lo;
    const int* idx;
    const float *wf, *wfb;
    float* logits;
    int Kdim, mode, HW, lvl_off, nrows, split;
};

// 16-warp do_chunk: warp tile 32 rows x 64 cols, acc[2][8][4]
__device__ __forceinline__ void do_chunk(uint32_t sb, int lane, int wm, int wn,
                                         float acc[2][8][4]){
    const int lm_r = (lane & 7) + ((lane >> 3) & 1) * 8;
    const int lm_k = (lane >> 4) * 16;
#pragma unroll
    for (int ks = 0; ks < 4; ks++) {
        const int kb = ks * 32 + lm_k;
        uint32_t ah[2][4], al[2][4];
#pragma unroll
        for (int mi = 0; mi < 2; mi++) {
            int row = wm * 32 + mi * 16 + lm_r;
            uint32_t so = sw128((uint32_t)(row * 128 + kb));
            ldsm4(sb + AH_OFF + so, ah[mi][0], ah[mi][1], ah[mi][2], ah[mi][3]);
            ldsm4(sb + AL_OFF + so, al[mi][0], al[mi][1], al[mi][2], al[mi][3]);
        }
#pragma unroll
        for (int bi = 0; bi < 4; bi++) {
            int nr = wn * 64 + bi * 16 + lm_r;
            uint32_t so = sw128((uint32_t)(nr * 128 + kb));
            uint32_t bh0,bh1,bh2,bh3, bl0,bl1,bl2,bl3;
            ldsm4(sb + BH_OFF + so, bh0,bh1,bh2,bh3);
            ldsm4(sb + BL_OFF + so, bl0,bl1,bl2,bl3);
#pragma unroll
            for (int mi=0;mi<2;mi++) mma_bf16(acc[mi][2*bi],   ah[mi], bh0, bh2);
#pragma unroll
            for (int mi=0;mi<2;mi++) mma_bf16(acc[mi][2*bi+1], ah[mi], bh1, bh3);
#pragma unroll
            for (int mi=0;mi<2;mi++) mma_bf16(acc[mi][2*bi],   ah[mi], bl0, bl2);
#pragma unroll
            for (int mi=0;mi<2;mi++) mma_bf16(acc[mi][2*bi+1], ah[mi], bl1, bl3);
#pragma unroll
            for (int mi=0;mi<2;mi++) mma_bf16(acc[mi][2*bi],   al[mi], bh0, bh2);
#pragma unroll
            for (int mi=0;mi<2;mi++) mma_bf16(acc[mi][2*bi+1], al[mi], bh1, bh3);
        }
    }
}

// ============================================================================
// tc_gemm (512 threads, 16 warps): D[128-row tile, 256] = X @ W (bf16x3).
// mode 0: +bias -> LN -> SiLU (or fused final dot if wf).
// mode 1: lateral conv + BN. mode 2: gathered rows.
// blockIdx >= split selects second param set (cls/box pairing).
// ============================================================================
__global__ __launch_bounds__(512) void tc_gemm(GArgs a)
{
    extern __shared__ char smem[];
    const uint32_t sbase = smem_u32(smem);
    const int tid  = threadIdx.x;
    const int lane = tid & 31;
    const int wid  = tid >> 5;
    const int wm   = wid >> 2;   // 0..3, 32-row band
    const int wn   = wid & 3;    // 0..3, 64-col slice
    const int mode = a.mode;

    int blk = blockIdx.x;
    const __nv_bfloat16 *Ahi = a.Ahi, *Alo = a.Alo, *Whi = a.Whi, *Wlo = a.Wlo;
    const float *pb = a.pb, *pg = a.pg, *po = a.po;
    __nv_bfloat16 *Yhi = a.Yhi, *Ylo = a.Ylo;
    if (blk >= a.split) {
        blk -= a.split;
        Ahi = a.A2hi; Alo = a.A2lo; Whi = a.W2hi; Wlo = a.W2lo;
        pb = a.pb2; pg = a.pg2; po = a.po2; Yhi = a.Y2hi; Ylo = a.Y2lo;
    }
    const int row0 = blk * 128;

    // params -> smem
    if (tid < 256) {
        if (mode == 1) {
            float sc = a.pg[tid] * rsqrtf(a.pv[tid] + LN_EPS);
            ((float*)(smem+P_PG))[tid] = sc;
            ((float*)(smem+P_PO))[tid] = a.po[tid] - a.pm[tid] * sc;
        } else {
            ((float*)(smem+P_PB))[tid] = pb[tid];
            ((float*)(smem+P_PG))[tid] = pg[tid];
            ((float*)(smem+P_PO))[tid] = po[tid];
            if (a.wf) ((float*)(smem+P_WF))[tid] = a.wf[tid];
        }
    }
    if (tid < 128) {
        ((float*)(smem+P_RS))[tid] = 0.f;
        ((float*)(smem+P_RQ))[tid] = 0.f;
        ((float*)(smem+P_RD))[tid] = 0.f;
        int i = row0 + tid; if (i >= a.nrows) i = a.nrows - 1;
        int gl = (mode == 2) ? (i / KINST) * NTOK + a.idx[i] : i;
        ((int*)(smem+P_SIDX))[tid] = gl;
    }
    __syncthreads();

    const int* sidx = (const int*)(smem + P_SIDX);
    const int nch = a.Kdim >> 6;

    float acc[2][8][4];
#pragma unroll
    for (int mi = 0; mi < 2; mi++)
#pragma unroll
        for (int ni = 0; ni < 8; ni++)
#pragma unroll
            for (int q = 0; q < 4; q++) acc[mi][ni][q] = 0.f;

    auto issueA = [&](int kc, int stg){
        const int k0 = kc * 64;
        const uint32_t sb = sbase + stg * STAGE;
#pragma unroll
        for (int j = 0; j < 2; j++) {
            int u = tid + j * 512;
            int r = u >> 3, s = u & 7;
            size_t off = (size_t)sidx[r] * 256 + k0 + s * 8;
            uint32_t d = sb + AH_OFF + sw128((uint32_t)(r * 128 + s * 16));
            cpasync16(d, Ahi + off);
            cpasync16(d + (AL_OFF - AH_OFF), Alo + off);
        }
    };
    auto issueB = [&](int kc, int stg){
        const int k0 = kc * 64;
        const uint32_t sb = sbase + stg * STAGE;
#pragma unroll
        for (int j = 0; j < 4; j++) {
            int u = tid + j * 512;
            int o = u >> 3, s = u & 7;
            size_t off = (size_t)o * a.Kdim + k0 + s * 8;
            uint32_t d = sb + BH_OFF + sw128((uint32_t)(o * 128 + s * 16));
            cpasync16(d, Whi + off);
            cpasync16(d + (BL_OFF - BH_OFF), Wlo + off);
        }
    };

    int bb_lat = 0, hw0 = 0;
    if (mode == 1) { bb_lat = row0 / a.HW; hw0 = row0 % a.HW; }

    if (mode != 1) {
        issueA(0, 0); issueB(0, 0); cp_commit();
        issueA(1, 1); issueB(1, 1); cp_commit();
        for (int kc = 0; kc < nch; kc++) {
            const int stg = kc & 1;
            asm volatile("cp.async.wait_group 1;" ::: "memory");
            __syncthreads();
            do_chunk(sbase + stg * STAGE, lane, wm, wn, acc);
            __syncthreads();
            if (kc + 2 < nch) { issueA(kc + 2, stg); issueB(kc + 2, stg); }
            cp_commit();
        }
    } else {
        for (int kc = 0; kc < nch; kc++) {
            const int k0 = kc * 64;
            issueB(kc, 0); cp_commit();
            // convert A (fp32 [Cin,HW]) into stage 0 (overlaps W cp.async)
#pragma unroll
            for (int j = 0; j < 4; j++) {
                int f = tid + j * 512;
                int kk = f >> 5, r4 = (f & 31) * 4;
                float4 v = *(const float4*)(a.Xf + ((size_t)(bb_lat * a.Kdim + k0 + kk)) * a.HW + hw0 + r4);
                float xs[4] = { v.x, v.y, v.z, v.w };
#pragma unroll
                for (int t = 0; t < 4; t++) {
                    __nv_bfloat16 h = __float2bfloat16(xs[t]);
                    __nv_bfloat16 l = __float2bfloat16(xs[t] - __bfloat162float(h));
                    uint32_t so = sw128((uint32_t)((r4 + t) * 128 + kk * 2));
                    *(unsigned short*)(smem + AH_OFF + so) = __bfloat16_as_ushort(h);
                    *(unsigned short*)(smem + AL_OFF + so) = __bfloat16_as_ushort(l);
                }
            }
            asm volatile("cp.async.wait_group 0;" ::: "memory");
            __syncthreads();
            do_chunk(sbase, lane, wm, wn, acc);
            __syncthreads();
        }
    }

    // ---- epilogue ----
    const float* f_bias = (float*)(smem + P_PB);
    const float* f_g    = (float*)(smem + P_PG);
    const float* f_o    = (float*)(smem + P_PO);
    const float* f_wf   = (float*)(smem + P_WF);
    float* rowsum = (float*)(smem + P_RS);
    float* rowsq  = (float*)(smem + P_RQ);
    float* rowdot = (float*)(smem + P_RD);
    const int rloc = lane >> 2;

    if (mode == 1) {
#pragma unroll
        for (int mi = 0; mi < 2; mi++) {
            int rA = wm * 32 + mi * 16 + rloc;
            int rB = rA + 8;
            size_t oA = (size_t)bb_lat * NTOK + a.lvl_off + hw0 + rA;
            size_t oB = oA + 8;
#pragma unroll
            for (int ni = 0; ni < 8; ni++) {
                int c0 = wn * 64 + ni * 8 + (lane & 3) * 2;
                float g0 = f_g[c0], g1 = f_g[c0+1], o0 = f_o[c0], o1 = f_o[c0+1];
                store_hl2(Yhi, Ylo, oA, c0, acc[mi][ni][0]*g0+o0, acc[mi][ni][1]*g1+o1);
                store_hl2(Yhi, Ylo, oB, c0, acc[mi][ni][2]*g0+o0, acc[mi][ni][3]*g1+o1);
            }
        }
        return;
    }

    // mode 0/2: bias add + row stats
#pragma unroll
    for (int mi = 0; mi < 2; mi++) {
        float sA=0.f, qA=0.f, sB=0.f, qB=0.f;
#pragma unroll
        for (int ni = 0; ni < 8; ni++) {
            int c0 = wn * 64 + ni * 8 + (lane & 3) * 2;
            float b0 = f_bias[c0], b1 = f_bias[c0+1];
            float v0 = acc[mi][ni][0] + b0;
            float v1 = acc[mi][ni][1] + b1;
            float v2 = acc[mi][ni][2] + b0;
            float v3 = acc[mi][ni][3] + b1;
            acc[mi][ni][0]=v0; acc[mi][ni][1]=v1; acc[mi][ni][2]=v2; acc[mi][ni][3]=v3;
            sA += v0 + v1; qA += v0*v0 + v1*v1;
            sB += v2 + v3; qB += v2*v2 + v3*v3;
        }
#pragma unroll
        for (int o = 1; o <= 2; o <<= 1) {
            sA += __shfl_xor_sync(0xffffffffu, sA, o);
            qA += __shfl_xor_sync(0xffffffffu, qA, o);
            sB += __shfl_xor_sync(0xffffffffu, sB, o);
            qB += __shfl_xor_sync(0xffffffffu, qB, o);
        }
        if ((lane & 3) == 0) {
            int rA = wm * 32 + mi * 16 + rloc;
            atomicAdd(&rowsum[rA], sA);   atomicAdd(&rowsq[rA], qA);
            atomicAdd(&rowsum[rA+8], sB); atomicAdd(&rowsq[rA+8], qB);
        }
    }
    __syncthreads();

    if (a.wf) {
        // fused loc final: LN -> SiLU -> dot(Wf)
#pragma unroll
        for (int mi = 0; mi < 2; mi++) {
            int rA = wm * 32 + mi * 16 + rloc;
            int rB = rA + 8;
            float mA = rowsum[rA] * (1.f/256.f);
            float rsA = rsqrtf(rowsq[rA] * (1.f/256.f) - mA*mA + LN_EPS);
            float mB = rowsum[rB] * (1.f/256.f);
            float rsB = rsqrtf(rowsq[rB] * (1.f/256.f) - mB*mB + LN_EPS);
            float pA = 0.f, pB = 0.f;
#pragma unroll
            for (int ni = 0; ni < 8; ni++) {
                int c0 = wn * 64 + ni * 8 + (lane & 3) * 2;
                float g0=f_g[c0], g1=f_g[c0+1], o0=f_o[c0], o1=f_o[c0+1];
                float u0 = (acc[mi][ni][0]-mA)*rsA*g0 + o0;
                float u1 = (acc[mi][ni][1]-mA)*rsA*g1 + o1;
                float u2 = (acc[mi][ni][2]-mB)*rsB*g0 + o0;
                float u3 = (acc[mi][ni][3]-mB)*rsB*g1 + o1;
                u0 = u0/(1.f+expf(-u0)); u1 = u1/(1.f+expf(-u1));
                u2 = u2/(1.f+expf(-u2)); u3 = u3/(1.f+expf(-u3));
                pA += u0*f_wf[c0] + u1*f_wf[c0+1];
                pB += u2*f_wf[c0] + u3*f_wf[c0+1];
            }
#pragma unroll
            for (int o = 1; o <= 2; o <<= 1) {
                pA += __shfl_xor_sync(0xffffffffu, pA, o);
                pB += __shfl_xor_sync(0xffffffffu, pB, o);
            }
            if ((lane & 3) == 0) {
                atomicAdd(&rowdot[rA], pA);
                atomicAdd(&rowdot[rB], pB);
            }
        }
        __syncthreads();
        if (tid < 128) {
            int rg = row0 + tid;
            if (rg < a.nrows) a.logits[rg] = rowdot[tid] + a.wfb[0];
        }
    } else {
#pragma unroll
        for (int mi = 0; mi < 2; mi++) {
            int rA = wm * 32 + mi * 16 + rloc;
            int rB = rA + 8;
            float mA = rowsum[rA] * (1.f/256.f);
            float rsA = rsqrtf(rowsq[rA] * (1.f/256.f) - mA*mA + LN_EPS);
            float mB = rowsum[rB] * (1.f/256.f);
            float rsB = rsqrtf(rowsq[rB] * (1.f/256.f) - mB*mB + LN_EPS);
            int rgA = row0 + rA, rgB = row0 + rB;
#pragma unroll
            for (int ni = 0; ni < 8; ni++) {
                int c0 = wn * 64 + ni * 8 + (lane & 3) * 2;
                float g0=f_g[c0], g1=f_g[c0+1], o0=f_o[c0], o1=f_o[c0+1];
                float u0 = (acc[mi][ni][0]-mA)*rsA*g0 + o0;
                float u1 = (acc[mi][ni][1]-mA)*rsA*g1 + o1;
                float u2 = (acc[mi][ni][2]-mB)*rsB*g0 + o0;
                float u3 = (acc[mi][ni][3]-mB)*rsB*g1 + o1;
                u0 = u0/(1.f+expf(-u0)); u1 = u1/(1.f+expf(-u1));
                u2 = u2/(1.f+expf(-u2)); u3 = u3/(1.f+expf(-u3));
                if (rgA < a.nrows) store_hl2(Yhi, Ylo, (size_t)rgA, c0, u0, u1);
                if (rgB < a.nrows) store_hl2(Yhi, Ylo, (size_t)rgB, c0, u2, u3);
            }
        }
    }
}

// ---------------- weight prep: head mats [K,O] -> bf16 hi/lo [O,K] ----------
__global__ __launch_bounds__(256) void prep_tr(
    const float* __restrict__ locw, const float* __restrict__ clsw,
    const float* __restrict__ boxw, __nv_bfloat16* __restrict__ hi,
    __nv_bfloat16* __restrict__ lo)
{
    int mat = blockIdx.x >> 8;
    int o   = blockIdx.x & 255;
    int k   = threadIdx.x;
    const float* W = (mat < 4 ? locw : (mat < 8 ? clsw : boxw)) + (size_t)(mat & 3) * 65536;
    float v = W[k * 256 + o];
    __nv_bfloat16 h = __float2bfloat16(v);
    size_t oi = (size_t)mat * 65536 + (size_t)o * 256 + k;
    hi[oi] = h;
    lo[oi] = __float2bfloat16(v - __bfloat162float(h));
}

__global__ __launch_bounds__(256) void prep_direct(
    const float* __restrict__ W, __nv_bfloat16* __restrict__ hi,
    __nv_bfloat16* __restrict__ lo, int n)
{
    int i = blockIdx.x * 256 + threadIdx.x;
    if (i < n) {
        float v = W[i];
        __nv_bfloat16 h = __float2bfloat16(v);
        hi[i] = h;
        lo[i] = __float2bfloat16(v - __bfloat162float(h));
    }
}

// ---------------- top-k ----------------
__global__ __launch_bounds__(512) void topk_kernel(
    const float* __restrict__ logits, float* __restrict__ vals, int* __restrict__ idxs)
{
    __shared__ float sv[NTOK];
    __shared__ float rv[16];
    __shared__ int   ri[16];
    const int b = blockIdx.x, tid = threadIdx.x;
    for (int i = tid; i < NTOK; i += 512) sv[i] = logits[b * NTOK + i];
    __syncthreads();
    for (int k = 0; k < KINST; k++) {
        float bv = -3.0e38f; int bi = 0;
        for (int i = tid; i < NTOK; i += 512) {
            float v = sv[i];
            if (v > bv) { bv = v; bi = i; }
        }
#pragma unroll
        for (int o = 16; o > 0; o >>= 1) {
            float ov = __shfl_xor_sync(0xffffffffu, bv, o);
            int   oi = __shfl_xor_sync(0xffffffffu, bi, o);
            if (ov > bv || (ov == bv && oi < bi)) { bv = ov; bi = oi; }
        }
        if ((tid & 31) == 0) { rv[tid >> 5] = bv; ri[tid >> 5] = bi; }
        __syncthreads();
        if (tid == 0) {
            for (int w = 1; w < 16; w++)
                if (rv[w] > bv || (rv[w] == bv && ri[w] < bi)) { bv = rv[w]; bi = ri[w]; }
            vals[b * KINST + k] = bv;
            idxs[b * KINST + k] = bi;
            sv[bi] = -3.3e38f;
        }
        __syncthreads();
    }
}

__device__ __forceinline__ float read_dim(const int* p) {
    int v = p[0];
    if (v > 0 && v < 1000000) return (float)v;
    return __int_as_float(v);
}

// ---------------- merged finals: cls argmax + box decode ----------------
__global__ __launch_bounds__(128) void finals_kernel(
    const __nv_bfloat16* __restrict__ chi, const __nv_bfloat16* __restrict__ clo,
    const __nv_bfloat16* __restrict__ bhi, const __nv_bfloat16* __restrict__ blo,
    const float* __restrict__ clsWf, const float* __restrict__ clsbf,
    const float* __restrict__ boxWf, const float* __restrict__ boxbf,
    const int* __restrict__ idxs, const int* __restrict__ p_fh,
    const int* __restrict__ p_fw, float* __restrict__ out)
{
    __shared__ float xc[256], xb[256], sval[80], e[4];
    int i = blockIdx.x, tid = threadIdx.x, lane = tid & 31, w = tid >> 5;
    {
        size_t base = (size_t)i * 256;
        xc[tid]     = __bfloat162float(chi[base+tid])     + __bfloat162float(clo[base+tid]);
        xc[tid+128] = __bfloat162float(chi[base+tid+128]) + __bfloat162float(clo[base+tid+128]);
        xb[tid]     = __bfloat162float(bhi[base+tid])     + __bfloat162float(blo[base+tid]);
        xb[tid+128] = __bfloat162float(bhi[base+tid+128]) + __bfloat162float(blo[base+tid+128]);
    }
    __syncthreads();
    float s = 0.f;
#pragma unroll
    for (int j = 0; j < 8; j++) {
        int k = lane + j * 32;
        s = fmaf(xb[k], boxWf[k * 4 + w], s);
    }
#pragma unroll
    for (int o = 16; o > 0; o >>= 1) s += __shfl_xor_sync(0xffffffffu, s, o);
    if (lane == 0) e[w] = expf(s + boxbf[w]);
    if (tid < 80) {
        float s2 = clsbf[tid];
        for (int k = 0; k < 256; k++) s2 = fmaf(xc[k], clsWf[k * 80 + tid], s2);
        sval[tid] = s2;
    }
    __syncthreads();
    if (tid == 0) {
        float bv = sval[0]; int bi = 0;
        for (int t = 1; t < 80; t++) if (sval[t] > bv) { bv = sval[t]; bi = t; }
        out[CL_OFF + i] = (float)bi;

        int n = idxs[i];
        int hsz, m;
        if (n < 4096)      { hsz = 64; m = n; }
        else if (n < 5120) { hsz = 32; m = n - 4096; }
        else               { hsz = 16; m = n - 5120; }
        int gy = m / hsz, gx = m % hsz;
        float inv = 1.0f / (float)hsz;
        float ox = (gx + 0.5f) * inv, oy = (gy + 0.5f) * inv;
        float half = 0.5f * inv;
        float fw = read_dim(p_fw), fh = read_dim(p_fh);
        float* o4 = out + BX_OFF + (size_t)i * 4;
        o4[0] = (ox - half * e[0]) * fw;
        o4[1] = (oy - half * e[1]) * fh;
        o4[2] = (ox + half * e[2]) * fw;
        o4[3] = (oy + half * e[3]) * fh;
    }
}

// ---------------- scores + num_instances ----------------
__global__ __launch_bounds__(800) void scores_kernel(
    const float* __restrict__ vals, float* __restrict__ out)
{
    __shared__ int cnt[BATCH];
    int tid = threadIdx.x;
    if (tid < BATCH) cnt[tid] = 0;
    __syncthreads();
    float v = vals[tid];
    out[SC_OFF + tid] = 1.f / (1.f + expf(-v));
    if (v > 0.f) atomicAdd(&cnt[tid / KINST], 1);
    __syncthreads();
    if (tid < BATCH) out[NI_OFF + tid] = (float)cnt[tid];
}

// ---------------- host launcher ----------------
extern "C" void kernel_launch(void* const* d_in, const int* in_sizes, int n_in,
                              void* d_out, int out_size)
{
    const float* x3     = (const float*)d_in[0];
    const float* x4     = (const float*)d_in[1];
    const float* x5     = (const float*)d_in[2];
    const float* lat_w3 = (const float*)d_in[3];
    const float* lat_w4 = (const float*)d_in[4];
    const float* lat_w5 = (const float*)d_in[5];
    const float* bn_g   = (const float*)d_in[6];
    const float* bn_b   = (const float*)d_in[7];
    const float* bn_m   = (const float*)d_in[8];
    const float* bn_v   = (const float*)d_in[9];
    const float* loc_Ws = (const float*)d_in[10];
    const float* loc_bs = (const float*)d_in[11];
    const float* loc_lng= (const float*)d_in[12];
    const float* loc_lnb= (const float*)d_in[13];
    const float* loc_Wf = (const float*)d_in[14];
    const float* loc_bf = (const float*)d_in[15];
    const float* cls_Ws = (const float*)d_in[16];
    const float* cls_bs = (const float*)d_in[17];
    const float* cls_lng= (const float*)d_in[18];
    const float* cls_lnb= (const float*)d_in[19];
    const float* cls_Wf = (const float*)d_in[20];
    const float* cls_bf = (const float*)d_in[21];
    const float* box_Ws = (const float*)d_in[22];
    const float* box_bs = (const float*)d_in[23];
    const float* box_lng= (const float*)d_in[24];
    const float* box_lnb= (const float*)d_in[25];
    const float* box_Wf = (const float*)d_in[26];
    const float* box_bf = (const float*)d_in[27];
    const int*   p_fh   = (const int*)d_in[28];
    const int*   p_fw   = (const int*)d_in[29];
    float* out = (float*)d_out;

    __nv_bfloat16 *flathi, *flatlo, *p0hi, *p0lo, *p1hi, *p1lo, *hd, *whi, *wlo, *lathi, *latlo;
    float *logits, *vals; int* idxp;
    cudaGetSymbolAddress((void**)&flathi, g_flathi);
    cudaGetSymbolAddress((void**)&flatlo, g_flatlo);
    cudaGetSymbolAddress((void**)&p0hi,   g_p0hi);
    cudaGetSymbolAddress((void**)&p0lo,   g_p0lo);
    cudaGetSymbolAddress((void**)&p1hi,   g_p1hi);
    cudaGetSymbolAddress((void**)&p1lo,   g_p1lo);
    cudaGetSymbolAddress((void**)&logits, g_logits);
    cudaGetSymbolAddress((void**)&vals,   g_vals);
    cudaGetSymbolAddress((void**)&idxp,   g_idx);
    cudaGetSymbolAddress((void**)&hd,     g_hd);
    cudaGetSymbolAddress((void**)&whi,    g_whi);
    cudaGetSymbolAddress((void**)&wlo,    g_wlo);
    cudaGetSymbolAddress((void**)&lathi,  g_lathi);
    cudaGetSymbolAddress((void**)&latlo,  g_latlo);

    const size_t HP = 896 * 256;
    __nv_bfloat16* c0hi = hd + 0*HP; __nv_bfloat16* c0lo = hd + 1*HP;
    __nv_bfloat16* c1hi = hd + 2*HP; __nv_bfloat16* c1lo = hd + 3*HP;
    __nv_bfloat16* b0hi = hd + 4*HP; __nv_bfloat16* b0lo = hd + 5*HP;
    __nv_bfloat16* b1hi = hd + 6*HP; __nv_bfloat16* b1lo = hd + 7*HP;

    cudaFuncSetAttribute(tc_gemm, cudaFuncAttributeMaxDynamicSharedMemorySize, SMEM_TOTAL);

    // 0) weight prep
    prep_tr<<<12*256, 256>>>(loc_Ws, cls_Ws, box_Ws, whi, wlo);
    prep_direct<<<(65536+255)/256, 256>>>(lat_w3, lathi, latlo, 65536);
    prep_direct<<<(131072+255)/256, 256>>>(lat_w4, lathi + 65536, latlo + 65536, 131072);
    prep_direct<<<(262144+255)/256, 256>>>(lat_w5, lathi + 196608, latlo + 196608, 262144);

    GArgs a; memset(&a, 0, sizeof(a));
    a.split = 1 << 30;

    // 1) laterals -> flat planes (mode 1)
    {
        GArgs L = a; L.mode = 1;
        L.Xf = x3; L.Whi = lathi; L.Wlo = latlo; L.Kdim = 256; L.HW = 4096; L.lvl_off = 0;
        L.pg = bn_g + 0*C; L.po = bn_b + 0*C; L.pm = bn_m + 0*C; L.pv = bn_v + 0*C;
        L.Yhi = flathi; L.Ylo = flatlo; L.nrows = BATCH*4096;
        tc_gemm<<<BATCH*4096/128, 512, SMEM_TOTAL>>>(L);
        L.Xf = x4; L.Whi = lathi + 65536; L.Wlo = latlo + 65536; L.Kdim = 512; L.HW = 1024; L.lvl_off = 4096;
        L.pg = bn_g + 1*C; L.po = bn_b + 1*C; L.pm = bn_m + 1*C; L.pv = bn_v + 1*C;
        L.nrows = BATCH*1024;
        tc_gemm<<<BATCH*1024/128, 512, SMEM_TOTAL>>>(L);
        L.Xf = x5; L.Whi = lathi + 196608; L.Wlo = latlo + 196608; L.Kdim = 1024; L.HW = 256; L.lvl_off = 5120;
        L.pg = bn_g + 2*C; L.po = bn_b + 2*C; L.pm = bn_m + 2*C; L.pv = bn_v + 2*C;
        L.nrows = BATCH*256;
        tc_gemm<<<BATCH*256/128, 512, SMEM_TOTAL>>>(L);
    }

    // 2) loc MLP: 4 layers, layer 4 fused with final dot -> logits
    {
        const __nv_bfloat16* curhi = flathi;
        const __nv_bfloat16* curlo = flatlo;
        __nv_bfloat16* phi[2] = { p0hi, p1hi };
        __nv_bfloat16* plo[2] = { p0lo, p1lo };
        for (int i = 0; i < 4; i++) {
            GArgs L = a; L.mode = 0; L.Kdim = 256; L.nrows = TOT;
            L.Ahi = curhi; L.Alo = curlo;
            L.Whi = whi + (size_t)i*65536; L.Wlo = wlo + (size_t)i*65536;
            L.pb = loc_bs + i*C; L.pg = loc_lng + i*C; L.po = loc_lnb + i*C;
            if (i == 3) { L.wf = loc_Wf; L.wfb = loc_bf; L.logits = logits; }
            else { L.Yhi = phi[i & 1]; L.Ylo = plo[i & 1]; }
            tc_gemm<<<TOT/128, 512, SMEM_TOTAL>>>(L);
            curhi = phi[i & 1]; curlo = plo[i & 1];
        }
    }

    // 3) top-k
    topk_kernel<<<BATCH, 512>>>(logits, vals, idxp);

    // 4) heads: 4 combined cls+box layers (grid 14, split 7); layer 1 = fused gather
    {
        const __nv_bfloat16 *cAhi = flathi, *cAlo = flatlo, *bAhi = flathi, *bAlo = flatlo;
        __nv_bfloat16 *cY[2][2] = { {c0hi, c0lo}, {c1hi, c1lo} };
        __nv_bfloat16 *bY[2][2] = { {b0hi, b0lo}, {b1hi, b1lo} };
        for (int i = 0; i < 4; i++) {
            GArgs L = a; L.mode = (i == 0) ? 2 : 0; L.Kdim = 256; L.nrows = 800; L.split = 7;
            L.idx = idxp;
            L.Ahi = cAhi;  L.Alo = cAlo;
            L.A2hi = bAhi; L.A2lo = bAlo;
            L.Whi  = whi + (size_t)(4+i)*65536; L.Wlo  = wlo + (size_t)(4+i)*65536;
            L.W2hi = whi + (size_t)(8+i)*65536; L.W2lo = wlo + (size_t)(8+i)*65536;
            L.pb = cls_bs + i*C;  L.pg = cls_lng + i*C;  L.po = cls_lnb + i*C;
            L.pb2 = box_bs + i*C; L.pg2 = box_lng + i*C; L.po2 = box_lnb + i*C;
            L.Yhi = cY[i & 1][0];  L.Ylo = cY[i & 1][1];
            L.Y2hi = bY[i & 1][0]; L.Y2lo = bY[i & 1][1];
            tc_gemm<<<14, 512, SMEM_TOTAL>>>(L);
            cAhi = cY[i & 1][0]; cAlo = cY[i & 1][1];
            bAhi = bY[i & 1][0]; bAlo = bY[i & 1][1];
        }
    }

    // 5) finals + scores
    finals_kernel<<<800, 128>>>(c1hi, c1lo, b1hi, b1lo,
        cls_Wf, cls_bf, box_Wf, box_bf, idxp, p_fh, p_fw, out);
    scores_kernel<<<1, 800>>>(vals, out);
}

// round 7
// speedup vs baseline: 1.8347x; 1.1103x over previous
#include <cuda_runtime.h>
#include <cuda_bf16.h>
#include <math.h>
#include <string.h>
#include <stdint.h>

#define C 256
#define BATCH 8
#define NTOK 5376
#define TOT (BATCH*NTOK)   /* 43008 */
#define KINST 100
#define LN_EPS 1e-5f

#define NI_OFF 0
#define SC_OFF 8
#define CL_OFF 808
#define BX_OFF 1608

// ---------------- device scratch ----------------
__device__ __nv_bfloat16 g_flathi[TOT*C], g_flatlo[TOT*C];
__device__ __nv_bfloat16 g_p0hi[TOT*C],  g_p0lo[TOT*C];
__device__ __nv_bfloat16 g_p1hi[TOT*C],  g_p1lo[TOT*C];
__device__ float g_logits[TOT];
__device__ float g_vals[BATCH*KINST];
__device__ int   g_idx[BATCH*KINST];
__device__ __nv_bfloat16 g_hd[8][896*256];
__device__ __nv_bfloat16 g_whi[12*65536];
__device__ __nv_bfloat16 g_wlo[12*65536];
__device__ __nv_bfloat16 g_lathi[458752];
__device__ __nv_bfloat16 g_latlo[458752];

// ---------------- helpers ----------------
__device__ __forceinline__ uint32_t smem_u32(const void* p){
    uint32_t a;
    asm("{ .reg .u64 t; cvta.to.shared.u64 t, %1; cvt.u32.u64 %0, t; }" : "=r"(a) : "l"(p));
    return a;
}
__device__ __forceinline__ uint32_t sw128(uint32_t o){ return o ^ ((o >> 3) & 0x70); }

__device__ __forceinline__ void ldsm4(uint32_t addr, uint32_t& r0, uint32_t& r1,
                                      uint32_t& r2, uint32_t& r3){
    asm volatile("ldmatrix.sync.aligned.m8n8.x4.shared.b16 {%0,%1,%2,%3}, [%4];"
                 : "=r"(r0), "=r"(r1), "=r"(r2), "=r"(r3) : "r"(addr));
}
__device__ __forceinline__ void mma_bf16(float* d, const uint32_t* a, uint32_t b0, uint32_t b1){
    asm volatile(
        "mma.sync.aligned.m16n8k16.row.col.f32.bf16.bf16.f32 "
        "{%0,%1,%2,%3}, {%4,%5,%6,%7}, {%8,%9}, {%0,%1,%2,%3};"
        : "+f"(d[0]), "+f"(d[1]), "+f"(d[2]), "+f"(d[3])
        : "r"(a[0]), "r"(a[1]), "r"(a[2]), "r"(a[3]), "r"(b0), "r"(b1));
}
__device__ __forceinline__ void cpasync16(uint32_t dst, const void* src){
    asm volatile("cp.async.cg.shared.global [%0], [%1], 16;" :: "r"(dst), "l"(src));
}
__device__ __forceinline__ void cp_commit(){
    asm volatile("cp.async.commit_group;" ::: "memory");
}
__device__ __forceinline__ void store_hl2(__nv_bfloat16* Yhi, __nv_bfloat16* Ylo,
                                          size_t row, int c0, float u0, float u1){
    __nv_bfloat16 h0=__float2bfloat16(u0), h1=__float2bfloat16(u1);
    __nv_bfloat16 l0=__float2bfloat16(u0-__bfloat162float(h0));
    __nv_bfloat16 l1=__float2bfloat16(u1-__bfloat162float(h1));
    __nv_bfloat162 hh; hh.x=h0; hh.y=h1;
    __nv_bfloat162 ll; ll.x=l0; ll.y=l1;
    *(__nv_bfloat162*)(Yhi+row*256+c0) = hh;
    *(__nv_bfloat162*)(Ylo+row*256+c0) = ll;
}

// ---------------- smem layout (bytes) ----------------
#define STAGE   98304
#define AH_OFF  0
#define AL_OFF  16384
#define BH_OFF  32768
#define BL_OFF  65536
#define P_PB    196608
#define P_PG    197632
#define P_PO    198656
#define P_WF    199680
#define P_RS    200704
#define P_RQ    201216
#define P_RD    201728
#define P_SIDX  202240
#define SMEM_TOTAL 202752

// 16-warp do_chunk: warp tile 32 rows x 64 cols, acc[2][8][4]
__device__ __forceinline__ void do_chunk(uint32_t sb, int lane, int wm, int wn,
                                         float acc[2][8][4]){
    const int lm_r = (lane & 7) + ((lane >> 3) & 1) * 8;
    const int lm_k = (lane >> 4) * 16;
#pragma unroll
    for (int ks = 0; ks < 4; ks++) {
        const int kb = ks * 32 + lm_k;
        uint32_t ah[2][4], al[2][4];
#pragma unroll
        for (int mi = 0; mi < 2; mi++) {
            int row = wm * 32 + mi * 16 + lm_r;
            uint32_t so = sw128((uint32_t)(row * 128 + kb));
            ldsm4(sb + AH_OFF + so, ah[mi][0], ah[mi][1], ah[mi][2], ah[mi][3]);
            ldsm4(sb + AL_OFF + so, al[mi][0], al[mi][1], al[mi][2], al[mi][3]);
        }
#pragma unroll
        for (int bi = 0; bi < 4; bi++) {
            int nr = wn * 64 + bi * 16 + lm_r;
            uint32_t so = sw128((uint32_t)(nr * 128 + kb));
            uint32_t bh0,bh1,bh2,bh3, bl0,bl1,bl2,bl3;
            ldsm4(sb + BH_OFF + so, bh0,bh1,bh2,bh3);
            ldsm4(sb + BL_OFF + so, bl0,bl1,bl2,bl3);
#pragma unroll
            for (int mi=0;mi<2;mi++) mma_bf16(acc[mi][2*bi],   ah[mi], bh0, bh2);
#pragma unroll
            for (int mi=0;mi<2;mi++) mma_bf16(acc[mi][2*bi+1], ah[mi], bh1, bh3);
#pragma unroll
            for (int mi=0;mi<2;mi++) mma_bf16(acc[mi][2*bi],   ah[mi], bl0, bl2);
#pragma unroll
            for (int mi=0;mi<2;mi++) mma_bf16(acc[mi][2*bi+1], ah[mi], bl1, bl3);
#pragma unroll
            for (int mi=0;mi<2;mi++) mma_bf16(acc[mi][2*bi],   al[mi], bh0, bh2);
#pragma unroll
            for (int mi=0;mi<2;mi++) mma_bf16(acc[mi][2*bi+1], al[mi], bh1, bh3);
        }
    }
}

struct GArgs {
    const __nv_bfloat16 *Ahi, *Alo, *A2hi, *A2lo;
    const __nv_bfloat16 *Whi, *Wlo, *W2hi, *W2lo;
    const float *pb, *pg, *po;
    const float *pb2, *pg2, *po2;
    __nv_bfloat16 *Yhi, *Ylo, *Y2hi, *Y2lo;
    const int* idx;
    const float *wf, *wfb;
    float* logits;
    int Kdim, mode, nrows, split;
};

// ============================================================================
// tc_gemm (512 threads, 16 warps): D[128-row tile, 256] = X @ W (bf16x3).
// mode 0: +bias -> LN -> SiLU (or fused final dot if wf). mode 2: gathered rows.
// blockIdx >= split selects second param set (cls/box pairing).
// ============================================================================
__global__ __launch_bounds__(512) void tc_gemm(GArgs a)
{
    extern __shared__ char smem[];
    const uint32_t sbase = smem_u32(smem);
    const int tid  = threadIdx.x;
    const int lane = tid & 31;
    const int wid  = tid >> 5;
    const int wm   = wid >> 2;
    const int wn   = wid & 3;
    const int mode = a.mode;

    int blk = blockIdx.x;
    const __nv_bfloat16 *Ahi = a.Ahi, *Alo = a.Alo, *Whi = a.Whi, *Wlo = a.Wlo;
    const float *pb = a.pb, *pg = a.pg, *po = a.po;
    __nv_bfloat16 *Yhi = a.Yhi, *Ylo = a.Ylo;
    if (blk >= a.split) {
        blk -= a.split;
        Ahi = a.A2hi; Alo = a.A2lo; Whi = a.W2hi; Wlo = a.W2lo;
        pb = a.pb2; pg = a.pg2; po = a.po2; Yhi = a.Y2hi; Ylo = a.Y2lo;
    }
    const int row0 = blk * 128;

    if (tid < 256) {
        ((float*)(smem+P_PB))[tid] = pb[tid];
        ((float*)(smem+P_PG))[tid] = pg[tid];
        ((float*)(smem+P_PO))[tid] = po[tid];
        if (a.wf) ((float*)(smem+P_WF))[tid] = a.wf[tid];
    }
    if (tid < 128) {
        ((float*)(smem+P_RS))[tid] = 0.f;
        ((float*)(smem+P_RQ))[tid] = 0.f;
        ((float*)(smem+P_RD))[tid] = 0.f;
        int i = row0 + tid; if (i >= a.nrows) i = a.nrows - 1;
        int gl = (mode == 2) ? (i / KINST) * NTOK + a.idx[i] : i;
        ((int*)(smem+P_SIDX))[tid] = gl;
    }
    __syncthreads();

    const int* sidx = (const int*)(smem + P_SIDX);
    const int nch = a.Kdim >> 6;

    float acc[2][8][4];
#pragma unroll
    for (int mi = 0; mi < 2; mi++)
#pragma unroll
        for (int ni = 0; ni < 8; ni++)
#pragma unroll
            for (int q = 0; q < 4; q++) acc[mi][ni][q] = 0.f;

    auto issueA = [&](int kc, int stg){
        const int k0 = kc * 64;
        const uint32_t sb = sbase + stg * STAGE;
#pragma unroll
        for (int j = 0; j < 2; j++) {
            int u = tid + j * 512;
            int r = u >> 3, s = u & 7;
            size_t off = (size_t)sidx[r] * 256 + k0 + s * 8;
            uint32_t d = sb + AH_OFF + sw128((uint32_t)(r * 128 + s * 16));
            cpasync16(d, Ahi + off);
            cpasync16(d + (AL_OFF - AH_OFF), Alo + off);
        }
    };
    auto issueB = [&](int kc, int stg){
        const int k0 = kc * 64;
        const uint32_t sb = sbase + stg * STAGE;
#pragma unroll
        for (int j = 0; j < 4; j++) {
            int u = tid + j * 512;
            int o = u >> 3, s = u & 7;
            size_t off = (size_t)o * a.Kdim + k0 + s * 8;
            uint32_t d = sb + BH_OFF + sw128((uint32_t)(o * 128 + s * 16));
            cpasync16(d, Whi + off);
            cpasync16(d + (BL_OFF - BH_OFF), Wlo + off);
        }
    };

    issueA(0, 0); issueB(0, 0); cp_commit();
    issueA(1, 1); issueB(1, 1); cp_commit();
    for (int kc = 0; kc < nch; kc++) {
        const int stg = kc & 1;
        asm volatile("cp.async.wait_group 1;" ::: "memory");
        __syncthreads();
        do_chunk(sbase + stg * STAGE, lane, wm, wn, acc);
        __syncthreads();
        if (kc + 2 < nch) { issueA(kc + 2, stg); issueB(kc + 2, stg); }
        cp_commit();
    }

    // ---- epilogue ----
    const float* f_bias = (float*)(smem + P_PB);
    const float* f_g    = (float*)(smem + P_PG);
    const float* f_o    = (float*)(smem + P_PO);
    const float* f_wf   = (float*)(smem + P_WF);
    float* rowsum = (float*)(smem + P_RS);
    float* rowsq  = (float*)(smem + P_RQ);
    float* rowdot = (float*)(smem + P_RD);
    const int rloc = lane >> 2;

#pragma unroll
    for (int mi = 0; mi < 2; mi++) {
        float sA=0.f, qA=0.f, sB=0.f, qB=0.f;
#pragma unroll
        for (int ni = 0; ni < 8; ni++) {
            int c0 = wn * 64 + ni * 8 + (lane & 3) * 2;
            float b0 = f_bias[c0], b1 = f_bias[c0+1];
            float v0 = acc[mi][ni][0] + b0;
            float v1 = acc[mi][ni][1] + b1;
            float v2 = acc[mi][ni][2] + b0;
            float v3 = acc[mi][ni][3] + b1;
            acc[mi][ni][0]=v0; acc[mi][ni][1]=v1; acc[mi][ni][2]=v2; acc[mi][ni][3]=v3;
            sA += v0 + v1; qA += v0*v0 + v1*v1;
            sB += v2 + v3; qB += v2*v2 + v3*v3;
        }
#pragma unroll
        for (int o = 1; o <= 2; o <<= 1) {
            sA += __shfl_xor_sync(0xffffffffu, sA, o);
            qA += __shfl_xor_sync(0xffffffffu, qA, o);
            sB += __shfl_xor_sync(0xffffffffu, sB, o);
            qB += __shfl_xor_sync(0xffffffffu, qB, o);
        }
        if ((lane & 3) == 0) {
            int rA = wm * 32 + mi * 16 + rloc;
            atomicAdd(&rowsum[rA], sA);   atomicAdd(&rowsq[rA], qA);
            atomicAdd(&rowsum[rA+8], sB); atomicAdd(&rowsq[rA+8], qB);
        }
    }
    __syncthreads();

    if (a.wf) {
#pragma unroll
        for (int mi = 0; mi < 2; mi++) {
            int rA = wm * 32 + mi * 16 + rloc;
            int rB = rA + 8;
            float mA = rowsum[rA] * (1.f/256.f);
            float rsA = rsqrtf(rowsq[rA] * (1.f/256.f) - mA*mA + LN_EPS);
            float mB = rowsum[rB] * (1.f/256.f);
            float rsB = rsqrtf(rowsq[rB] * (1.f/256.f) - mB*mB + LN_EPS);
            float pA = 0.f, pB = 0.f;
#pragma unroll
            for (int ni = 0; ni < 8; ni++) {
                int c0 = wn * 64 + ni * 8 + (lane & 3) * 2;
                float g0=f_g[c0], g1=f_g[c0+1], o0=f_o[c0], o1=f_o[c0+1];
                float u0 = (acc[mi][ni][0]-mA)*rsA*g0 + o0;
                float u1 = (acc[mi][ni][1]-mA)*rsA*g1 + o1;
                float u2 = (acc[mi][ni][2]-mB)*rsB*g0 + o0;
                float u3 = (acc[mi][ni][3]-mB)*rsB*g1 + o1;
                u0 = u0/(1.f+expf(-u0)); u1 = u1/(1.f+expf(-u1));
                u2 = u2/(1.f+expf(-u2)); u3 = u3/(1.f+expf(-u3));
                pA += u0*f_wf[c0] + u1*f_wf[c0+1];
                pB += u2*f_wf[c0] + u3*f_wf[c0+1];
            }
#pragma unroll
            for (int o = 1; o <= 2; o <<= 1) {
                pA += __shfl_xor_sync(0xffffffffu, pA, o);
                pB += __shfl_xor_sync(0xffffffffu, pB, o);
            }
            if ((lane & 3) == 0) {
                atomicAdd(&rowdot[rA], pA);
                atomicAdd(&rowdot[rB], pB);
            }
        }
        __syncthreads();
        if (tid < 128) {
            int rg = row0 + tid;
            if (rg < a.nrows) a.logits[rg] = rowdot[tid] + a.wfb[0];
        }
    } else {
#pragma unroll
        for (int mi = 0; mi < 2; mi++) {
            int rA = wm * 32 + mi * 16 + rloc;
            int rB = rA + 8;
            float mA = rowsum[rA] * (1.f/256.f);
            float rsA = rsqrtf(rowsq[rA] * (1.f/256.f) - mA*mA + LN_EPS);
            float mB = rowsum[rB] * (1.f/256.f);
            float rsB = rsqrtf(rowsq[rB] * (1.f/256.f) - mB*mB + LN_EPS);
            int rgA = row0 + rA, rgB = row0 + rB;
#pragma unroll
            for (int ni = 0; ni < 8; ni++) {
                int c0 = wn * 64 + ni * 8 + (lane & 3) * 2;
                float g0=f_g[c0], g1=f_g[c0+1], o0=f_o[c0], o1=f_o[c0+1];
                float u0 = (acc[mi][ni][0]-mA)*rsA*g0 + o0;
                float u1 = (acc[mi][ni][1]-mA)*rsA*g1 + o1;
                float u2 = (acc[mi][ni][2]-mB)*rsB*g0 + o0;
                float u3 = (acc[mi][ni][3]-mB)*rsB*g1 + o1;
                u0 = u0/(1.f+expf(-u0)); u1 = u1/(1.f+expf(-u1));
                u2 = u2/(1.f+expf(-u2)); u3 = u3/(1.f+expf(-u3));
                if (rgA < a.nrows) store_hl2(Yhi, Ylo, (size_t)rgA, c0, u0, u1);
                if (rgB < a.nrows) store_hl2(Yhi, Ylo, (size_t)rgB, c0, u2, u3);
            }
        }
    }
}

// ============================================================================
// lat_gemm: all 3 lateral levels in ONE launch (336 CTAs), software-pipelined:
// A fp32 loads register-staged one chunk ahead; B double-buffered cp.async.
// ============================================================================
struct LatArgs {
    const float *x3, *x4, *x5;
    const __nv_bfloat16 *Whi, *Wlo;
    const float *bn_g, *bn_b, *bn_m, *bn_v;
    __nv_bfloat16 *Yhi, *Ylo;
};

__global__ __launch_bounds__(512) void lat_gemm(LatArgs a)
{
    extern __shared__ char smem[];
    const uint32_t sbase = smem_u32(smem);
    const int tid = threadIdx.x, lane = tid & 31, wid = tid >> 5;
    const int wm = wid >> 2, wn = wid & 3;

    int blk = blockIdx.x;
    const float* Xf; int Kdim, HW, lvl_off, wofs, lv;
    if (blk < 256)      { lv=0; Xf=a.x3; Kdim=256;  HW=4096; lvl_off=0;    wofs=0; }
    else if (blk < 320) { lv=1; blk-=256; Xf=a.x4; Kdim=512;  HW=1024; lvl_off=4096; wofs=65536; }
    else                { lv=2; blk-=320; Xf=a.x5; Kdim=1024; HW=256;  lvl_off=5120; wofs=196608; }
    const __nv_bfloat16* Whi = a.Whi + wofs;
    const __nv_bfloat16* Wlo = a.Wlo + wofs;
    const int row0 = blk * 128;
    const int bb = row0 / HW, hw0 = row0 % HW;

    if (tid < 256) {
        float sc = a.bn_g[lv*C + tid] * rsqrtf(a.bn_v[lv*C + tid] + LN_EPS);
        ((float*)(smem+P_PG))[tid] = sc;
        ((float*)(smem+P_PO))[tid] = a.bn_b[lv*C + tid] - a.bn_m[lv*C + tid] * sc;
    }
    __syncthreads();

    float acc[2][8][4];
#pragma unroll
    for (int mi = 0; mi < 2; mi++)
#pragma unroll
        for (int ni = 0; ni < 8; ni++)
#pragma unroll
            for (int q = 0; q < 4; q++) acc[mi][ni][q] = 0.f;

    float4 areg[4];
    auto loadA = [&](int kc){
#pragma unroll
        for (int j = 0; j < 4; j++) {
            int f = tid + j * 512;
            int kk = f >> 5, r4 = (f & 31) * 4;
            areg[j] = *(const float4*)(Xf + ((size_t)(bb * Kdim + kc * 64 + kk)) * HW + hw0 + r4);
        }
    };
    auto convA = [&](int stg){
        const uint32_t base = (uint32_t)(stg * STAGE);
#pragma unroll
        for (int j = 0; j < 4; j++) {
            int f = tid + j * 512;
            int kk = f >> 5, r4 = (f & 31) * 4;
            float xs[4] = { areg[j].x, areg[j].y, areg[j].z, areg[j].w };
#pragma unroll
            for (int t = 0; t < 4; t++) {
                __nv_bfloat16 h = __float2bfloat16(xs[t]);
                __nv_bfloat16 l = __float2bfloat16(xs[t] - __bfloat162float(h));
                uint32_t so = base + sw128((uint32_t)((r4 + t) * 128 + kk * 2));
                *(unsigned short*)(smem + AH_OFF + so) = __bfloat16_as_ushort(h);
                *(unsigned short*)(smem + AL_OFF + so) = __bfloat16_as_ushort(l);
            }
        }
    };
    auto issueB = [&](int kc, int stg){
        const int k0 = kc * 64;
        const uint32_t sb = sbase + stg * STAGE;
#pragma unroll
        for (int j = 0; j < 4; j++) {
            int u = tid + j * 512;
            int o = u >> 3, s = u & 7;
            size_t off = (size_t)o * Kdim + k0 + s * 8;
            uint32_t d = sb + BH_OFF + sw128((uint32_t)(o * 128 + s * 16));
            cpasync16(d, Whi + off);
            cpasync16(d + (BL_OFF - BH_OFF), Wlo + off);
        }
    };

    const int nch = Kdim >> 6;
    // pipeline fill
    loadA(0); issueB(0, 0); cp_commit();
    convA(0);
    if (nch > 1) { loadA(1); issueB(1, 1); }
    cp_commit();

    for (int kc = 0; kc < nch; kc++) {
        const int stg = kc & 1;
        asm volatile("cp.async.wait_group 1;" ::: "memory");
        __syncthreads();
        do_chunk(sbase + stg * STAGE, lane, wm, wn, acc);
        __syncthreads();
        if (kc + 1 < nch) convA((kc + 1) & 1);
        if (kc + 2 < nch) { loadA(kc + 2); issueB(kc + 2, stg); }
        cp_commit();
    }

    const float* f_g = (float*)(smem + P_PG);
    const float* f_o = (float*)(smem + P_PO);
    const int rloc = lane >> 2;
#pragma unroll
    for (int mi = 0; mi < 2; mi++) {
        int rA = wm * 32 + mi * 16 + rloc;
        int rB = rA + 8;
        size_t oA = (size_t)bb * NTOK + lvl_off + hw0 + rA;
        size_t oB = oA + 8;
#pragma unroll
        for (int ni = 0; ni < 8; ni++) {
            int c0 = wn * 64 + ni * 8 + (lane & 3) * 2;
            float g0 = f_g[c0], g1 = f_g[c0+1], o0 = f_o[c0], o1 = f_o[c0+1];
            store_hl2(a.Yhi, a.Ylo, oA, c0, acc[mi][ni][0]*g0+o0, acc[mi][ni][1]*g1+o1);
            store_hl2(a.Yhi, a.Ylo, oB, c0, acc[mi][ni][2]*g0+o0, acc[mi][ni][3]*g1+o1);
        }
    }
}

// ---------------- merged weight prep (one launch) ----------------
__global__ __launch_bounds__(256) void prep_all(
    const float* __restrict__ locw, const float* __restrict__ clsw,
    const float* __restrict__ boxw, __nv_bfloat16* __restrict__ whi,
    __nv_bfloat16* __restrict__ wlo,
    const float* __restrict__ lw3, const float* __restrict__ lw4,
    const float* __restrict__ lw5, __nv_bfloat16* __restrict__ lhi,
    __nv_bfloat16* __restrict__ llo)
{
    int blk = blockIdx.x;
    if (blk < 3072) {
        int mat = blk >> 8, o = blk & 255, k = threadIdx.x;
        const float* W = (mat < 4 ? locw : (mat < 8 ? clsw : boxw)) + (size_t)(mat & 3) * 65536;
        float v = W[k * 256 + o];
        __nv_bfloat16 h = __float2bfloat16(v);
        size_t oi = (size_t)mat * 65536 + (size_t)o * 256 + k;
        whi[oi] = h;
        wlo[oi] = __float2bfloat16(v - __bfloat162float(h));
    } else {
        int i = (blk - 3072) * 256 + threadIdx.x;
        float v = (i < 65536) ? lw3[i] : (i < 196608 ? lw4[i - 65536] : lw5[i - 196608]);
        __nv_bfloat16 h = __float2bfloat16(v);
        lhi[i] = h;
        llo[i] = __float2bfloat16(v - __bfloat162float(h));
    }
}

// ---------------- top-k (register-resident local maxima) ----------------
__global__ __launch_bounds__(512) void topk_kernel(
    const float* __restrict__ logits, float* __restrict__ vals, int* __restrict__ idxs)
{
    __shared__ float sv[NTOK];
    __shared__ float rv[16];
    __shared__ int   ri[16];
    __shared__ float wbv;
    __shared__ int   wbi;
    const int b = blockIdx.x, tid = threadIdx.x, lane = tid & 31, wd = tid >> 5;
    for (int i = tid; i < NTOK; i += 512) sv[i] = logits[b * NTOK + i];
    __syncthreads();

    // per-thread local max over strided strip
    float bv = -3.0e38f; int bi = tid;
    for (int i = tid; i < NTOK; i += 512) {
        float v = sv[i];
        if (v > bv) { bv = v; bi = i; }
    }

    for (int k = 0; k < KINST; k++) {
        float tv = bv; int ti = bi;
#pragma unroll
        for (int o = 16; o > 0; o >>= 1) {
            float ov = __shfl_xor_sync(0xffffffffu, tv, o);
            int   oi = __shfl_xor_sync(0xffffffffu, ti, o);
            if (ov > tv || (ov == tv && oi < ti)) { tv = ov; ti = oi; }
        }
        if (lane == 0) { rv[wd] = tv; ri[wd] = ti; }
        __syncthreads();
        if (wd == 0) {
            float xv = (lane < 16) ? rv[lane] : -3.3e38f;
            int   xi = (lane < 16) ? ri[lane] : 0;
#pragma unroll
            for (int o = 8; o > 0; o >>= 1) {
                float ov = __shfl_xor_sync(0xffffffffu, xv, o);
                int   oi = __shfl_xor_sync(0xffffffffu, xi, o);
                if (ov > xv || (ov == xv && oi < xi)) { xv = ov; xi = oi; }
            }
            if (lane == 0) {
                vals[b * KINST + k] = xv;
                idxs[b * KINST + k] = xi;
                wbv = xv; wbi = xi;
            }
        }
        __syncthreads();
        int win = wbi;
        if (bi == win) {
            // this thread owned the winner: knock it out and rescan its strip
            sv[win] = -3.3e38f;
            bv = -3.0e38f; bi = tid;
            for (int i = tid; i < NTOK; i += 512) {
                float v = sv[i];
                if (v > bv) { bv = v; bi = i; }
            }
        }
    }
}

__device__ __forceinline__ float read_dim(const int* p) {
    int v = p[0];
    if (v > 0 && v < 1000000) return (float)v;
    return __int_as_float(v);
}

// ---------------- merged finals: cls argmax + box decode ----------------
__global__ __launch_bounds__(128) void finals_kernel(
    const __nv_bfloat16* __restrict__ chi, const __nv_bfloat16* __restrict__ clo,
    const __nv_bfloat16* __restrict__ bhi, const __nv_bfloat16* __restrict__ blo,
    const float* __restrict__ clsWf, const float* __restrict__ clsbf,
    const float* __restrict__ boxWf, const float* __restrict__ boxbf,
    const int* __restrict__ idxs, const int* __restrict__ p_fh,
    const int* __restrict__ p_fw, float* __restrict__ out)
{
    __shared__ float xc[256], xb[256], sval[80], e[4];
    int i = blockIdx.x, tid = threadIdx.x, lane = tid & 31, w = tid >> 5;
    {
        size_t base = (size_t)i * 256;
        xc[tid]     = __bfloat162float(chi[base+tid])     + __bfloat162float(clo[base+tid]);
        xc[tid+128] = __bfloat162float(chi[base+tid+128]) + __bfloat162float(clo[base+tid+128]);
        xb[tid]     = __bfloat162float(bhi[base+tid])     + __bfloat162float(blo[base+tid]);
        xb[tid+128] = __bfloat162float(bhi[base+tid+128]) + __bfloat162float(blo[base+tid+128]);
    }
    __syncthreads();
    float s = 0.f;
#pragma unroll
    for (int j = 0; j < 8; j++) {
        int k = lane + j * 32;
        s = fmaf(xb[k], boxWf[k * 4 + w], s);
    }
#pragma unroll
    for (int o = 16; o > 0; o >>= 1) s += __shfl_xor_sync(0xffffffffu, s, o);
    if (lane == 0) e[w] = expf(s + boxbf[w]);
    if (tid < 80) {
        float s2 = clsbf[tid];
        for (int k = 0; k < 256; k++) s2 = fmaf(xc[k], clsWf[k * 80 + tid], s2);
        sval[tid] = s2;
    }
    __syncthreads();
    if (tid == 0) {
        float bv = sval[0]; int bi = 0;
        for (int t = 1; t < 80; t++) if (sval[t] > bv) { bv = sval[t]; bi = t; }
        out[CL_OFF + i] = (float)bi;

        int n = idxs[i];
        int hsz, m;
        if (n < 4096)      { hsz = 64; m = n; }
        else if (n < 5120) { hsz = 32; m = n - 4096; }
        else               { hsz = 16; m = n - 5120; }
        int gy = m / hsz, gx = m % hsz;
        float inv = 1.0f / (float)hsz;
        float ox = (gx + 0.5f) * inv, oy = (gy + 0.5f) * inv;
        float half = 0.5f * inv;
        float fw = read_dim(p_fw), fh = read_dim(p_fh);
        float* o4 = out + BX_OFF + (size_t)i * 4;
        o4[0] = (ox - half * e[0]) * fw;
        o4[1] = (oy - half * e[1]) * fh;
        o4[2] = (ox + half * e[2]) * fw;
        o4[3] = (oy + half * e[3]) * fh;
    }
}

// ---------------- scores + num_instances ----------------
__global__ __launch_bounds__(800) void scores_kernel(
    const float* __restrict__ vals, float* __restrict__ out)
{
    __shared__ int cnt[BATCH];
    int tid = threadIdx.x;
    if (tid < BATCH) cnt[tid] = 0;
    __syncthreads();
    float v = vals[tid];
    out[SC_OFF + tid] = 1.f / (1.f + expf(-v));
    if (v > 0.f) atomicAdd(&cnt[tid / KINST], 1);
    __syncthreads();
    if (tid < BATCH) out[NI_OFF + tid] = (float)cnt[tid];
}

// ---------------- host launcher ----------------
extern "C" void kernel_launch(void* const* d_in, const int* in_sizes, int n_in,
                              void* d_out, int out_size)
{
    const float* x3     = (const float*)d_in[0];
    const float* x4     = (const float*)d_in[1];
    const float* x5     = (const float*)d_in[2];
    const float* lat_w3 = (const float*)d_in[3];
    const float* lat_w4 = (const float*)d_in[4];
    const float* lat_w5 = (const float*)d_in[5];
    const float* bn_g   = (const float*)d_in[6];
    const float* bn_b   = (const float*)d_in[7];
    const float* bn_m   = (const float*)d_in[8];
    const float* bn_v   = (const float*)d_in[9];
    const float* loc_Ws = (const float*)d_in[10];
    const float* loc_bs = (const float*)d_in[11];
    const float* loc_lng= (const float*)d_in[12];
    const float* loc_lnb= (const float*)d_in[13];
    const float* loc_Wf = (const float*)d_in[14];
    const float* loc_bf = (const float*)d_in[15];
    const float* cls_Ws = (const float*)d_in[16];
    const float* cls_bs = (const float*)d_in[17];
    const float* cls_lng= (const float*)d_in[18];
    const float* cls_lnb= (const float*)d_in[19];
    const float* cls_Wf = (const float*)d_in[20];
    const float* cls_bf = (const float*)d_in[21];
    const float* box_Ws = (const float*)d_in[22];
    const float* box_bs = (const float*)d_in[23];
    const float* box_lng= (const float*)d_in[24];
    const float* box_lnb= (const float*)d_in[25];
    const float* box_Wf = (const float*)d_in[26];
    const float* box_bf = (const float*)d_in[27];
    const int*   p_fh   = (const int*)d_in[28];
    const int*   p_fw   = (const int*)d_in[29];
    float* out = (float*)d_out;

    __nv_bfloat16 *flathi, *flatlo, *p0hi, *p0lo, *p1hi, *p1lo, *hd, *whi, *wlo, *lathi, *latlo;
    float *logits, *vals; int* idxp;
    cudaGetSymbolAddress((void**)&flathi, g_flathi);
    cudaGetSymbolAddress((void**)&flatlo, g_flatlo);
    cudaGetSymbolAddress((void**)&p0hi,   g_p0hi);
    cudaGetSymbolAddress((void**)&p0lo,   g_p0lo);
    cudaGetSymbolAddress((void**)&p1hi,   g_p1hi);
    cudaGetSymbolAddress((void**)&p1lo,   g_p1lo);
    cudaGetSymbolAddress((void**)&logits, g_logits);
    cudaGetSymbolAddress((void**)&vals,   g_vals);
    cudaGetSymbolAddress((void**)&idxp,   g_idx);
    cudaGetSymbolAddress((void**)&hd,     g_hd);
    cudaGetSymbolAddress((void**)&whi,    g_whi);
    cudaGetSymbolAddress((void**)&wlo,    g_wlo);
    cudaGetSymbolAddress((void**)&lathi,  g_lathi);
    cudaGetSymbolAddress((void**)&latlo,  g_latlo);

    const size_t HP = 896 * 256;
    __nv_bfloat16* c0hi = hd + 0*HP; __nv_bfloat16* c0lo = hd + 1*HP;
    __nv_bfloat16* c1hi = hd + 2*HP; __nv_bfloat16* c1lo = hd + 3*HP;
    __nv_bfloat16* b0hi = hd + 4*HP; __nv_bfloat16* b0lo = hd + 5*HP;
    __nv_bfloat16* b1hi = hd + 6*HP; __nv_bfloat16* b1lo = hd + 7*HP;

    cudaFuncSetAttribute(tc_gemm,  cudaFuncAttributeMaxDynamicSharedMemorySize, SMEM_TOTAL);
    cudaFuncSetAttribute(lat_gemm, cudaFuncAttributeMaxDynamicSharedMemorySize, SMEM_TOTAL);

    // 0) weight prep (one launch)
    prep_all<<<4864, 256>>>(loc_Ws, cls_Ws, box_Ws, whi, wlo,
                            lat_w3, lat_w4, lat_w5, lathi, latlo);

    // 1) laterals (one launch, 336 CTAs, pipelined)
    {
        LatArgs L;
        L.x3 = x3; L.x4 = x4; L.x5 = x5;
        L.Whi = lathi; L.Wlo = latlo;
        L.bn_g = bn_g; L.bn_b = bn_b; L.bn_m = bn_m; L.bn_v = bn_v;
        L.Yhi = flathi; L.Ylo = flatlo;
        lat_gemm<<<336, 512, SMEM_TOTAL>>>(L);
    }

    GArgs a; memset(&a, 0, sizeof(a));
    a.split = 1 << 30;

    // 2) loc MLP: 4 layers, layer 4 fused with final dot -> logits
    {
        const __nv_bfloat16* curhi = flathi;
        const __nv_bfloat16* curlo = flatlo;
        __nv_bfloat16* phi[2] = { p0hi, p1hi };
        __nv_bfloat16* plo[2] = { p0lo, p1lo };
        for (int i = 0; i < 4; i++) {
            GArgs L = a; L.mode = 0; L.Kdim = 256; L.nrows = TOT;
            L.Ahi = curhi; L.Alo = curlo;
            L.Whi = whi + (size_t)i*65536; L.Wlo = wlo + (size_t)i*65536;
            L.pb = loc_bs + i*C; L.pg = loc_lng + i*C; L.po = loc_lnb + i*C;
            if (i == 3) { L.wf = loc_Wf; L.wfb = loc_bf; L.logits = logits; }
            else { L.Yhi = phi[i & 1]; L.Ylo = plo[i & 1]; }
            tc_gemm<<<TOT/128, 512, SMEM_TOTAL>>>(L);
            curhi = phi[i & 1]; curlo = plo[i & 1];
        }
    }

    // 3) top-k
    topk_kernel<<<BATCH, 512>>>(logits, vals, idxp);

    // 4) heads: 4 combined cls+box layers (grid 14, split 7); layer 1 = fused gather
    {
        const __nv_bfloat16 *cAhi = flathi, *cAlo = flatlo, *bAhi = flathi, *bAlo = flatlo;
        __nv_bfloat16 *cY[2][2] = { {c0hi, c0lo}, {c1hi, c1lo} };
        __nv_bfloat16 *bY[2][2] = { {b0hi, b0lo}, {b1hi, b1lo} };
        for (int i = 0; i < 4; i++) {
            GArgs L = a; L.mode = (i == 0) ? 2 : 0; L.Kdim = 256; L.nrows = 800; L.split = 7;
            L.idx = idxp;
            L.Ahi = cAhi;  L.Alo = cAlo;
            L.A2hi = bAhi; L.A2lo = bAlo;
            L.Whi  = whi + (size_t)(4+i)*65536; L.Wlo  = wlo + (size_t)(4+i)*65536;
            L.W2hi = whi + (size_t)(8+i)*65536; L.W2lo = wlo + (size_t)(8+i)*65536;
            L.pb = cls_bs + i*C;  L.pg = cls_lng + i*C;  L.po = cls_lnb + i*C;
            L.pb2 = box_bs + i*C; L.pg2 = box_lng + i*C; L.po2 = box_lnb + i*C;
            L.Yhi = cY[i & 1][0];  L.Ylo = cY[i & 1][1];
            L.Y2hi = bY[i & 1][0]; L.Y2lo = bY[i & 1][1];
            tc_gemm<<<14, 512, SMEM_TOTAL>>>(L);
            cAhi = cY[i & 1][0]; cAlo = cY[i & 1][1];
            bAhi = bY[i & 1][0]; bAlo = bY[i & 1][1];
        }
    }

    // 5) finals + scores
    finals_kernel<<<800, 128>>>(c1hi, c1lo, b1hi, b1lo,
        cls_Wf, cls_bf, box_Wf, box_bf, idxp, p_fh, p_fw, out);
    scores_kernel<<<1, 800>>>(vals, out);
}

// round 8
// speedup vs baseline: 2.4230x; 1.3207x over previous
#include <cuda_runtime.h>
#include <cuda_bf16.h>
#include <math.h>
#include <string.h>
#include <stdint.h>

#define C 256
#define BATCH 8
#define NTOK 5376
#define TOT (BATCH*NTOK)   /* 43008 */
#define KINST 100
#define LN_EPS 1e-5f

#define NI_OFF 0
#define SC_OFF 8
#define CL_OFF 808
#define BX_OFF 1608

// ---------------- device scratch ----------------
__device__ __nv_bfloat16 g_flathi[TOT*C], g_flatlo[TOT*C];
__device__ __nv_bfloat16 g_p0hi[TOT*C],  g_p0lo[TOT*C];
__device__ __nv_bfloat16 g_p1hi[TOT*C],  g_p1lo[TOT*C];
__device__ float g_logits[TOT];
__device__ float g_vals[BATCH*KINST];
__device__ int   g_idx[BATCH*KINST];
__device__ __nv_bfloat16 g_hd[8][896*256];
__device__ __nv_bfloat16 g_whi[12*65536];
__device__ __nv_bfloat16 g_wlo[12*65536];
__device__ __nv_bfloat16 g_lathi[458752];
__device__ __nv_bfloat16 g_latlo[458752];

// ---------------- helpers ----------------
__device__ __forceinline__ uint32_t smem_u32(const void* p){
    uint32_t a;
    asm("{ .reg .u64 t; cvta.to.shared.u64 t, %1; cvt.u32.u64 %0, t; }" : "=r"(a) : "l"(p));
    return a;
}
__device__ __forceinline__ uint32_t sw128(uint32_t o){ return o ^ ((o >> 3) & 0x70); }

__device__ __forceinline__ void ldsm4(uint32_t addr, uint32_t& r0, uint32_t& r1,
                                      uint32_t& r2, uint32_t& r3){
    asm volatile("ldmatrix.sync.aligned.m8n8.x4.shared.b16 {%0,%1,%2,%3}, [%4];"
                 : "=r"(r0), "=r"(r1), "=r"(r2), "=r"(r3) : "r"(addr));
}
__device__ __forceinline__ void mma_bf16(float* d, const uint32_t* a, uint32_t b0, uint32_t b1){
    asm volatile(
        "mma.sync.aligned.m16n8k16.row.col.f32.bf16.bf16.f32 "
        "{%0,%1,%2,%3}, {%4,%5,%6,%7}, {%8,%9}, {%0,%1,%2,%3};"
        : "+f"(d[0]), "+f"(d[1]), "+f"(d[2]), "+f"(d[3])
        : "r"(a[0]), "r"(a[1]), "r"(a[2]), "r"(a[3]), "r"(b0), "r"(b1));
}
__device__ __forceinline__ void cpasync16(uint32_t dst, const void* src){
    asm volatile("cp.async.cg.shared.global [%0], [%1], 16;" :: "r"(dst), "l"(src));
}
__device__ __forceinline__ void cp_commit(){
    asm volatile("cp.async.commit_group;" ::: "memory");
}
__device__ __forceinline__ void store_hl2(__nv_bfloat16* Yhi, __nv_bfloat16* Ylo,
                                          size_t row, int c0, float u0, float u1){
    __nv_bfloat16 h0=__float2bfloat16(u0), h1=__float2bfloat16(u1);
    __nv_bfloat16 l0=__float2bfloat16(u0-__bfloat162float(h0));
    __nv_bfloat16 l1=__float2bfloat16(u1-__bfloat162float(h1));
    __nv_bfloat162 hh; hh.x=h0; hh.y=h1;
    __nv_bfloat162 ll; ll.x=l0; ll.y=l1;
    *(__nv_bfloat162*)(Yhi+row*256+c0) = hh;
    *(__nv_bfloat162*)(Ylo+row*256+c0) = ll;
}

// ---------------- smem layout (bytes), M=64 tile, single stage ----------------
#define AH_OFF  0         /* 64 x 128B  =  8KB */
#define AL_OFF  8192
#define BH_OFF  16384     /* 256 x 128B = 32KB */
#define BL_OFF  49152
#define P_PB    81920
#define P_PG    82944
#define P_PO    83968
#define P_WF    84992
#define P_RS    86016     /* 64 floats */
#define P_RQ    86272
#define P_RD    86528
#define P_SIDX  86784
#define SMEM_TOTAL 87040

// 8-warp do_chunk: warp tile 32 rows x 64 cols, acc[2][8][4]; wm in {0,1}
__device__ __forceinline__ void do_chunk(uint32_t sb, int lane, int wm, int wn,
                                         float acc[2][8][4]){
    const int lm_r = (lane & 7) + ((lane >> 3) & 1) * 8;
    const int lm_k = (lane >> 4) * 16;
#pragma unroll
    for (int ks = 0; ks < 4; ks++) {
        const int kb = ks * 32 + lm_k;
        uint32_t ah[2][4], al[2][4];
#pragma unroll
        for (int mi = 0; mi < 2; mi++) {
            int row = wm * 32 + mi * 16 + lm_r;
            uint32_t so = sw128((uint32_t)(row * 128 + kb));
            ldsm4(sb + AH_OFF + so, ah[mi][0], ah[mi][1], ah[mi][2], ah[mi][3]);
            ldsm4(sb + AL_OFF + so, al[mi][0], al[mi][1], al[mi][2], al[mi][3]);
        }
#pragma unroll
        for (int bi = 0; bi < 4; bi++) {
            int nr = wn * 64 + bi * 16 + lm_r;
            uint32_t so = sw128((uint32_t)(nr * 128 + kb));
            uint32_t bh0,bh1,bh2,bh3, bl0,bl1,bl2,bl3;
            ldsm4(sb + BH_OFF + so, bh0,bh1,bh2,bh3);
            ldsm4(sb + BL_OFF + so, bl0,bl1,bl2,bl3);
#pragma unroll
            for (int mi=0;mi<2;mi++) mma_bf16(acc[mi][2*bi],   ah[mi], bh0, bh2);
#pragma unroll
            for (int mi=0;mi<2;mi++) mma_bf16(acc[mi][2*bi+1], ah[mi], bh1, bh3);
#pragma unroll
            for (int mi=0;mi<2;mi++) mma_bf16(acc[mi][2*bi],   ah[mi], bl0, bl2);
#pragma unroll
            for (int mi=0;mi<2;mi++) mma_bf16(acc[mi][2*bi+1], ah[mi], bl1, bl3);
#pragma unroll
            for (int mi=0;mi<2;mi++) mma_bf16(acc[mi][2*bi],   al[mi], bh0, bh2);
#pragma unroll
            for (int mi=0;mi<2;mi++) mma_bf16(acc[mi][2*bi+1], al[mi], bh1, bh3);
        }
    }
}

struct GArgs {
    const __nv_bfloat16 *Ahi, *Alo, *A2hi, *A2lo;
    const __nv_bfloat16 *Whi, *Wlo, *W2hi, *W2lo;
    const float *pb, *pg, *po;
    const float *pb2, *pg2, *po2;
    __nv_bfloat16 *Yhi, *Ylo, *Y2hi, *Y2lo;
    const int* idx;
    const float *wf, *wfb;
    float* logits;
    int Kdim, mode, nrows, split;
};

// ============================================================================
// tc_gemm (256 threads, 8 warps, 2 CTAs/SM): D[64-row tile, 256] = X @ W.
// mode 0: +bias -> LN -> SiLU (or fused final dot if wf). mode 2: gathered rows.
// ============================================================================
__global__ __launch_bounds__(256, 2) void tc_gemm(GArgs a)
{
    extern __shared__ char smem[];
    const uint32_t sbase = smem_u32(smem);
    const int tid  = threadIdx.x;
    const int lane = tid & 31;
    const int wid  = tid >> 5;
    const int wm   = wid >> 2;   // 0..1, 32-row band
    const int wn   = wid & 3;    // 0..3, 64-col slice
    const int mode = a.mode;

    int blk = blockIdx.x;
    const __nv_bfloat16 *Ahi = a.Ahi, *Alo = a.Alo, *Whi = a.Whi, *Wlo = a.Wlo;
    const float *pb = a.pb, *pg = a.pg, *po = a.po;
    __nv_bfloat16 *Yhi = a.Yhi, *Ylo = a.Ylo;
    if (blk >= a.split) {
        blk -= a.split;
        Ahi = a.A2hi; Alo = a.A2lo; Whi = a.W2hi; Wlo = a.W2lo;
        pb = a.pb2; pg = a.pg2; po = a.po2; Yhi = a.Y2hi; Ylo = a.Y2lo;
    }
    const int row0 = blk * 64;

    ((float*)(smem+P_PB))[tid] = pb[tid];
    ((float*)(smem+P_PG))[tid] = pg[tid];
    ((float*)(smem+P_PO))[tid] = po[tid];
    if (a.wf) ((float*)(smem+P_WF))[tid] = a.wf[tid];
    if (tid < 64) {
        ((float*)(smem+P_RS))[tid] = 0.f;
        ((float*)(smem+P_RQ))[tid] = 0.f;
        ((float*)(smem+P_RD))[tid] = 0.f;
        int i = row0 + tid; if (i >= a.nrows) i = a.nrows - 1;
        int gl = (mode == 2) ? (i / KINST) * NTOK + a.idx[i] : i;
        ((int*)(smem+P_SIDX))[tid] = gl;
    }
    __syncthreads();

    const int* sidx = (const int*)(smem + P_SIDX);
    const int nch = a.Kdim >> 6;

    float acc[2][8][4];
#pragma unroll
    for (int mi = 0; mi < 2; mi++)
#pragma unroll
        for (int ni = 0; ni < 8; ni++)
#pragma unroll
            for (int q = 0; q < 4; q++) acc[mi][ni][q] = 0.f;

    auto issueA = [&](int kc){
        const int k0 = kc * 64;
#pragma unroll
        for (int j = 0; j < 2; j++) {
            int u = tid + j * 256;
            int r = u >> 3, s = u & 7;
            size_t off = (size_t)sidx[r] * 256 + k0 + s * 8;
            uint32_t d = sbase + AH_OFF + sw128((uint32_t)(r * 128 + s * 16));
            cpasync16(d, Ahi + off);
            cpasync16(d + (AL_OFF - AH_OFF), Alo + off);
        }
    };
    auto issueB = [&](int kc){
        const int k0 = kc * 64;
#pragma unroll
        for (int j = 0; j < 8; j++) {
            int u = tid + j * 256;
            int o = u >> 3, s = u & 7;
            size_t off = (size_t)o * a.Kdim + k0 + s * 8;
            uint32_t d = sbase + BH_OFF + sw128((uint32_t)(o * 128 + s * 16));
            cpasync16(d, Whi + off);
            cpasync16(d + (BL_OFF - BH_OFF), Wlo + off);
        }
    };

    // single-stage loop; 2 CTAs/SM hide each other's load phases
    for (int kc = 0; kc < nch; kc++) {
        if (kc > 0) __syncthreads();           // prev compute done before overwrite
        issueA(kc); issueB(kc); cp_commit();
        asm volatile("cp.async.wait_group 0;" ::: "memory");
        __syncthreads();
        do_chunk(sbase, lane, wm, wn, acc);
    }

    // ---- epilogue ----
    const float* f_bias = (float*)(smem + P_PB);
    const float* f_g    = (float*)(smem + P_PG);
    const float* f_o    = (float*)(smem + P_PO);
    const float* f_wf   = (float*)(smem + P_WF);
    float* rowsum = (float*)(smem + P_RS);
    float* rowsq  = (float*)(smem + P_RQ);
    float* rowdot = (float*)(smem + P_RD);
    const int rloc = lane >> 2;

#pragma unroll
    for (int mi = 0; mi < 2; mi++) {
        float sA=0.f, qA=0.f, sB=0.f, qB=0.f;
#pragma unroll
        for (int ni = 0; ni < 8; ni++) {
            int c0 = wn * 64 + ni * 8 + (lane & 3) * 2;
            float b0 = f_bias[c0], b1 = f_bias[c0+1];
            float v0 = acc[mi][ni][0] + b0;
            float v1 = acc[mi][ni][1] + b1;
            float v2 = acc[mi][ni][2] + b0;
            float v3 = acc[mi][ni][3] + b1;
            acc[mi][ni][0]=v0; acc[mi][ni][1]=v1; acc[mi][ni][2]=v2; acc[mi][ni][3]=v3;
            sA += v0 + v1; qA += v0*v0 + v1*v1;
            sB += v2 + v3; qB += v2*v2 + v3*v3;
        }
#pragma unroll
        for (int o = 1; o <= 2; o <<= 1) {
            sA += __shfl_xor_sync(0xffffffffu, sA, o);
            qA += __shfl_xor_sync(0xffffffffu, qA, o);
            sB += __shfl_xor_sync(0xffffffffu, sB, o);
            qB += __shfl_xor_sync(0xffffffffu, qB, o);
        }
        if ((lane & 3) == 0) {
            int rA = wm * 32 + mi * 16 + rloc;
            atomicAdd(&rowsum[rA], sA);   atomicAdd(&rowsq[rA], qA);
            atomicAdd(&rowsum[rA+8], sB); atomicAdd(&rowsq[rA+8], qB);
        }
    }
    __syncthreads();

    if (a.wf) {
#pragma unroll
        for (int mi = 0; mi < 2; mi++) {
            int rA = wm * 32 + mi * 16 + rloc;
            int rB = rA + 8;
            float mA = rowsum[rA] * (1.f/256.f);
            float rsA = rsqrtf(rowsq[rA] * (1.f/256.f) - mA*mA + LN_EPS);
            float mB = rowsum[rB] * (1.f/256.f);
            float rsB = rsqrtf(rowsq[rB] * (1.f/256.f) - mB*mB + LN_EPS);
            float pA = 0.f, pB = 0.f;
#pragma unroll
            for (int ni = 0; ni < 8; ni++) {
                int c0 = wn * 64 + ni * 8 + (lane & 3) * 2;
                float g0=f_g[c0], g1=f_g[c0+1], o0=f_o[c0], o1=f_o[c0+1];
                float u0 = (acc[mi][ni][0]-mA)*rsA*g0 + o0;
                float u1 = (acc[mi][ni][1]-mA)*rsA*g1 + o1;
                float u2 = (acc[mi][ni][2]-mB)*rsB*g0 + o0;
                float u3 = (acc[mi][ni][3]-mB)*rsB*g1 + o1;
                u0 = u0/(1.f+expf(-u0)); u1 = u1/(1.f+expf(-u1));
                u2 = u2/(1.f+expf(-u2)); u3 = u3/(1.f+expf(-u3));
                pA += u0*f_wf[c0] + u1*f_wf[c0+1];
                pB += u2*f_wf[c0] + u3*f_wf[c0+1];
            }
#pragma unroll
            for (int o = 1; o <= 2; o <<= 1) {
                pA += __shfl_xor_sync(0xffffffffu, pA, o);
                pB += __shfl_xor_sync(0xffffffffu, pB, o);
            }
            if ((lane & 3) == 0) {
                atomicAdd(&rowdot[rA], pA);
                atomicAdd(&rowdot[rB], pB);
            }
        }
        __syncthreads();
        if (tid < 64) {
            int rg = row0 + tid;
            if (rg < a.nrows) a.logits[rg] = rowdot[tid] + a.wfb[0];
        }
    } else {
#pragma unroll
        for (int mi = 0; mi < 2; mi++) {
            int rA = wm * 32 + mi * 16 + rloc;
            int rB = rA + 8;
            float mA = rowsum[rA] * (1.f/256.f);
            float rsA = rsqrtf(rowsq[rA] * (1.f/256.f) - mA*mA + LN_EPS);
            float mB = rowsum[rB] * (1.f/256.f);
            float rsB = rsqrtf(rowsq[rB] * (1.f/256.f) - mB*mB + LN_EPS);
            int rgA = row0 + rA, rgB = row0 + rB;
#pragma unroll
            for (int ni = 0; ni < 8; ni++) {
                int c0 = wn * 64 + ni * 8 + (lane & 3) * 2;
                float g0=f_g[c0], g1=f_g[c0+1], o0=f_o[c0], o1=f_o[c0+1];
                float u0 = (acc[mi][ni][0]-mA)*rsA*g0 + o0;
                float u1 = (acc[mi][ni][1]-mA)*rsA*g1 + o1;
                float u2 = (acc[mi][ni][2]-mB)*rsB*g0 + o0;
                float u3 = (acc[mi][ni][3]-mB)*rsB*g1 + o1;
                u0 = u0/(1.f+expf(-u0)); u1 = u1/(1.f+expf(-u1));
                u2 = u2/(1.f+expf(-u2)); u3 = u3/(1.f+expf(-u3));
                if (rgA < a.nrows) store_hl2(Yhi, Ylo, (size_t)rgA, c0, u0, u1);
                if (rgB < a.nrows) store_hl2(Yhi, Ylo, (size_t)rgB, c0, u2, u3);
            }
        }
    }
}

// ============================================================================
// lat_gemm: all 3 lateral levels in ONE launch (672 x M=64 CTAs, 2 CTAs/SM).
// A fp32 loads register-staged one chunk ahead; B single-stage cp.async.
// ============================================================================
struct LatArgs {
    const float *x3, *x4, *x5;
    const __nv_bfloat16 *Whi, *Wlo;
    const float *bn_g, *bn_b, *bn_m, *bn_v;
    __nv_bfloat16 *Yhi, *Ylo;
};

__global__ __launch_bounds__(256, 2) void lat_gemm(LatArgs a)
{
    extern __shared__ char smem[];
    const uint32_t sbase = smem_u32(smem);
    const int tid = threadIdx.x, lane = tid & 31, wid = tid >> 5;
    const int wm = wid >> 2, wn = wid & 3;

    int blk = blockIdx.x;
    const float* Xf; int Kdim, HW, lvl_off, wofs, lv;
    if (blk < 512)      { lv=0; Xf=a.x3; Kdim=256;  HW=4096; lvl_off=0;    wofs=0; }
    else if (blk < 640) { lv=1; blk-=512; Xf=a.x4; Kdim=512;  HW=1024; lvl_off=4096; wofs=65536; }
    else                { lv=2; blk-=640; Xf=a.x5; Kdim=1024; HW=256;  lvl_off=5120; wofs=196608; }
    const __nv_bfloat16* Whi = a.Whi + wofs;
    const __nv_bfloat16* Wlo = a.Wlo + wofs;
    const int row0 = blk * 64;
    const int bb = row0 / HW, hw0 = row0 % HW;

    {
        float sc = a.bn_g[lv*C + tid] * rsqrtf(a.bn_v[lv*C + tid] + LN_EPS);
        ((float*)(smem+P_PG))[tid] = sc;
        ((float*)(smem+P_PO))[tid] = a.bn_b[lv*C + tid] - a.bn_m[lv*C + tid] * sc;
    }
    __syncthreads();

    float acc[2][8][4];
#pragma unroll
    for (int mi = 0; mi < 2; mi++)
#pragma unroll
        for (int ni = 0; ni < 8; ni++)
#pragma unroll
            for (int q = 0; q < 4; q++) acc[mi][ni][q] = 0.f;

    float4 areg[4];
    auto loadA = [&](int kc){
#pragma unroll
        for (int j = 0; j < 4; j++) {
            int f = tid + j * 256;
            int kk = f >> 4, r4 = (f & 15) * 4;
            areg[j] = *(const float4*)(Xf + ((size_t)(bb * Kdim + kc * 64 + kk)) * HW + hw0 + r4);
        }
    };
    auto convA = [&](){
#pragma unroll
        for (int j = 0; j < 4; j++) {
            int f = tid + j * 256;
            int kk = f >> 4, r4 = (f & 15) * 4;
            float xs[4] = { areg[j].x, areg[j].y, areg[j].z, areg[j].w };
#pragma unroll
            for (int t = 0; t < 4; t++) {
                __nv_bfloat16 h = __float2bfloat16(xs[t]);
                __nv_bfloat16 l = __float2bfloat16(xs[t] - __bfloat162float(h));
                uint32_t so = sw128((uint32_t)((r4 + t) * 128 + kk * 2));
                *(unsigned short*)(smem + AH_OFF + so) = __bfloat16_as_ushort(h);
                *(unsigned short*)(smem + AL_OFF + so) = __bfloat16_as_ushort(l);
            }
        }
    };
    auto issueB = [&](int kc){
        const int k0 = kc * 64;
#pragma unroll
        for (int j = 0; j < 8; j++) {
            int u = tid + j * 256;
            int o = u >> 3, s = u & 7;
            size_t off = (size_t)o * Kdim + k0 + s * 8;
            uint32_t d = sbase + BH_OFF + sw128((uint32_t)(o * 128 + s * 16));
            cpasync16(d, Whi + off);
            cpasync16(d + (BL_OFF - BH_OFF), Wlo + off);
        }
    };

    const int nch = Kdim >> 6;
    loadA(0);
    for (int kc = 0; kc < nch; kc++) {
        if (kc > 0) __syncthreads();
        issueB(kc); cp_commit();
        convA();
        if (kc + 1 < nch) loadA(kc + 1);
        asm volatile("cp.async.wait_group 0;" ::: "memory");
        __syncthreads();
        do_chunk(sbase, lane, wm, wn, acc);
    }

    const float* f_g = (float*)(smem + P_PG);
    const float* f_o = (float*)(smem + P_PO);
    const int rloc = lane >> 2;
#pragma unroll
    for (int mi = 0; mi < 2; mi++) {
        int rA = wm * 32 + mi * 16 + rloc;
        int rB = rA + 8;
        size_t oA = (size_t)bb * NTOK + lvl_off + hw0 + rA;
        size_t oB = oA + 8;
#pragma unroll
        for (int ni = 0; ni < 8; ni++) {
            int c0 = wn * 64 + ni * 8 + (lane & 3) * 2;
            float g0 = f_g[c0], g1 = f_g[c0+1], o0 = f_o[c0], o1 = f_o[c0+1];
            store_hl2(a.Yhi, a.Ylo, oA, c0, acc[mi][ni][0]*g0+o0, acc[mi][ni][1]*g1+o1);
            store_hl2(a.Yhi, a.Ylo, oB, c0, acc[mi][ni][2]*g0+o0, acc[mi][ni][3]*g1+o1);
        }
    }
}

// ---------------- merged weight prep (one launch) ----------------
__global__ __launch_bounds__(256) void prep_all(
    const float* __restrict__ locw, const float* __restrict__ clsw,
    const float* __restrict__ boxw, __nv_bfloat16* __restrict__ whi,
    __nv_bfloat16* __restrict__ wlo,
    const float* __restrict__ lw3, const float* __restrict__ lw4,
    const float* __restrict__ lw5, __nv_bfloat16* __restrict__ lhi,
    __nv_bfloat16* __restrict__ llo)
{
    int blk = blockIdx.x;
    if (blk < 3072) {
        int mat = blk >> 8, o = blk & 255, k = threadIdx.x;
        const float* W = (mat < 4 ? locw : (mat < 8 ? clsw : boxw)) + (size_t)(mat & 3) * 65536;
        float v = W[k * 256 + o];
        __nv_bfloat16 h = __float2bfloat16(v);
        size_t oi = (size_t)mat * 65536 + (size_t)o * 256 + k;
        whi[oi] = h;
        wlo[oi] = __float2bfloat16(v - __bfloat162float(h));
    } else {
        int i = (blk - 3072) * 256 + threadIdx.x;
        float v = (i < 65536) ? lw3[i] : (i < 196608 ? lw4[i - 65536] : lw5[i - 196608]);
        __nv_bfloat16 h = __float2bfloat16(v);
        lhi[i] = h;
        llo[i] = __float2bfloat16(v - __bfloat162float(h));
    }
}

// ---------------- top-k (register-resident local maxima) ----------------
__global__ __launch_bounds__(512) void topk_kernel(
    const float* __restrict__ logits, float* __restrict__ vals, int* __restrict__ idxs)
{
    __shared__ float sv[NTOK];
    __shared__ float rv[16];
    __shared__ int   ri[16];
    __shared__ float wbv;
    __shared__ int   wbi;
    const int b = blockIdx.x, tid = threadIdx.x, lane = tid & 31, wd = tid >> 5;
    for (int i = tid; i < NTOK; i += 512) sv[i] = logits[b * NTOK + i];
    __syncthreads();

    float bv = -3.0e38f; int bi = tid;
    for (int i = tid; i < NTOK; i += 512) {
        float v = sv[i];
        if (v > bv) { bv = v; bi = i; }
    }

    for (int k = 0; k < KINST; k++) {
        float tv = bv; int ti = bi;
#pragma unroll
        for (int o = 16; o > 0; o >>= 1) {
            float ov = __shfl_xor_sync(0xffffffffu, tv, o);
            int   oi = __shfl_xor_sync(0xffffffffu, ti, o);
            if (ov > tv || (ov == tv && oi < ti)) { tv = ov; ti = oi; }
        }
        if (lane == 0) { rv[wd] = tv; ri[wd] = ti; }
        __syncthreads();
        if (wd == 0) {
            float xv = (lane < 16) ? rv[lane] : -3.3e38f;
            int   xi = (lane < 16) ? ri[lane] : 0;
#pragma unroll
            for (int o = 8; o > 0; o >>= 1) {
                float ov = __shfl_xor_sync(0xffffffffu, xv, o);
                int   oi = __shfl_xor_sync(0xffffffffu, xi, o);
                if (ov > xv || (ov == xv && oi < xi)) { xv = ov; xi = oi; }
            }
            if (lane == 0) {
                vals[b * KINST + k] = xv;
                idxs[b * KINST + k] = xi;
                wbv = xv; wbi = xi;
            }
        }
        __syncthreads();
        int win = wbi;
        if (bi == win) {
            sv[win] = -3.3e38f;
            bv = -3.0e38f; bi = tid;
            for (int i = tid; i < NTOK; i += 512) {
                float v = sv[i];
                if (v > bv) { bv = v; bi = i; }
            }
        }
    }
}

__device__ __forceinline__ float read_dim(const int* p) {
    int v = p[0];
    if (v > 0 && v < 1000000) return (float)v;
    return __int_as_float(v);
}

// ---------------- merged finals: cls argmax + box decode ----------------
__global__ __launch_bounds__(128) void finals_kernel(
    const __nv_bfloat16* __restrict__ chi, const __nv_bfloat16* __restrict__ clo,
    const __nv_bfloat16* __restrict__ bhi, const __nv_bfloat16* __restrict__ blo,
    const float* __restrict__ clsWf, const float* __restrict__ clsbf,
    const float* __restrict__ boxWf, const float* __restrict__ boxbf,
    const int* __restrict__ idxs, const int* __restrict__ p_fh,
    const int* __restrict__ p_fw, float* __restrict__ out)
{
    __shared__ float xc[256], xb[256], sval[80], e[4];
    int i = blockIdx.x, tid = threadIdx.x, lane = tid & 31, w = tid >> 5;
    {
        size_t base = (size_t)i * 256;
        xc[tid]     = __bfloat162float(chi[base+tid])     + __bfloat162float(clo[base+tid]);
        xc[tid+128] = __bfloat162float(chi[base+tid+128]) + __bfloat162float(clo[base+tid+128]);
        xb[tid]     = __bfloat162float(bhi[base+tid])     + __bfloat162float(blo[base+tid]);
        xb[tid+128] = __bfloat162float(bhi[base+tid+128]) + __bfloat162float(blo[base+tid+128]);
    }
    __syncthreads();
    float s = 0.f;
#pragma unroll
    for (int j = 0; j < 8; j++) {
        int k = lane + j * 32;
        s = fmaf(xb[k], boxWf[k * 4 + w], s);
    }
#pragma unroll
    for (int o = 16; o > 0; o >>= 1) s += __shfl_xor_sync(0xffffffffu, s, o);
    if (lane == 0) e[w] = expf(s + boxbf[w]);
    if (tid < 80) {
        float s2 = clsbf[tid];
        for (int k = 0; k < 256; k++) s2 = fmaf(xc[k], clsWf[k * 80 + tid], s2);
        sval[tid] = s2;
    }
    __syncthreads();
    if (tid == 0) {
        float bv = sval[0]; int bi = 0;
        for (int t = 1; t < 80; t++) if (sval[t] > bv) { bv = sval[t]; bi = t; }
        out[CL_OFF + i] = (float)bi;

        int n = idxs[i];
        int hsz, m;
        if (n < 4096)      { hsz = 64; m = n; }
        else if (n < 5120) { hsz = 32; m = n - 4096; }
        else               { hsz = 16; m = n - 5120; }
        int gy = m / hsz, gx = m % hsz;
        float inv = 1.0f / (float)hsz;
        float ox = (gx + 0.5f) * inv, oy = (gy + 0.5f) * inv;
        float half = 0.5f * inv;
        float fw = read_dim(p_fw), fh = read_dim(p_fh);
        float* o4 = out + BX_OFF + (size_t)i * 4;
        o4[0] = (ox - half * e[0]) * fw;
        o4[1] = (oy - half * e[1]) * fh;
        o4[2] = (ox + half * e[2]) * fw;
        o4[3] = (oy + half * e[3]) * fh;
    }
}

// ---------------- scores + num_instances ----------------
__global__ __launch_bounds__(800) void scores_kernel(
    const float* __restrict__ vals, float* __restrict__ out)
{
    __shared__ int cnt[BATCH];
    int tid = threadIdx.x;
    if (tid < BATCH) cnt[tid] = 0;
    __syncthreads();
    float v = vals[tid];
    out[SC_OFF + tid] = 1.f / (1.f + expf(-v));
    if (v > 0.f) atomicAdd(&cnt[tid / KINST], 1);
    __syncthreads();
    if (tid < BATCH) out[NI_OFF + tid] = (float)cnt[tid];
}

// ---------------- host launcher ----------------
extern "C" void kernel_launch(void* const* d_in, const int* in_sizes, int n_in,
                              void* d_out, int out_size)
{
    const float* x3     = (const float*)d_in[0];
    const float* x4     = (const float*)d_in[1];
    const float* x5     = (const float*)d_in[2];
    const float* lat_w3 = (const float*)d_in[3];
    const float* lat_w4 = (const float*)d_in[4];
    const float* lat_w5 = (const float*)d_in[5];
    const float* bn_g   = (const float*)d_in[6];
    const float* bn_b   = (const float*)d_in[7];
    const float* bn_m   = (const float*)d_in[8];
    const float* bn_v   = (const float*)d_in[9];
    const float* loc_Ws = (const float*)d_in[10];
    const float* loc_bs = (const float*)d_in[11];
    const float* loc_lng= (const float*)d_in[12];
    const float* loc_lnb= (const float*)d_in[13];
    const float* loc_Wf = (const float*)d_in[14];
    const float* loc_bf = (const float*)d_in[15];
    const float* cls_Ws = (const float*)d_in[16];
    const float* cls_bs = (const float*)d_in[17];
    const float* cls_lng= (const float*)d_in[18];
    const float* cls_lnb= (const float*)d_in[19];
    const float* cls_Wf = (const float*)d_in[20];
    const float* cls_bf = (const float*)d_in[21];
    const float* box_Ws = (const float*)d_in[22];
    const float* box_bs = (const float*)d_in[23];
    const float* box_lng= (const float*)d_in[24];
    const float* box_lnb= (const float*)d_in[25];
    const float* box_Wf = (const float*)d_in[26];
    const float* box_bf = (const float*)d_in[27];
    const int*   p_fh   = (const int*)d_in[28];
    const int*   p_fw   = (const int*)d_in[29];
    float* out = (float*)d_out;

    __nv_bfloat16 *flathi, *flatlo, *p0hi, *p0lo, *p1hi, *p1lo, *hd, *whi, *wlo, *lathi, *latlo;
    float *logits, *vals; int* idxp;
    cudaGetSymbolAddress((void**)&flathi, g_flathi);
    cudaGetSymbolAddress((void**)&flatlo, g_flatlo);
    cudaGetSymbolAddress((void**)&p0hi,   g_p0hi);
    cudaGetSymbolAddress((void**)&p0lo,   g_p0lo);
    cudaGetSymbolAddress((void**)&p1hi,   g_p1hi);
    cudaGetSymbolAddress((void**)&p1lo,   g_p1lo);
    cudaGetSymbolAddress((void**)&logits, g_logits);
    cudaGetSymbolAddress((void**)&vals,   g_vals);
    cudaGetSymbolAddress((void**)&idxp,   g_idx);
    cudaGetSymbolAddress((void**)&hd,     g_hd);
    cudaGetSymbolAddress((void**)&whi,    g_whi);
    cudaGetSymbolAddress((void**)&wlo,    g_wlo);
    cudaGetSymbolAddress((void**)&lathi,  g_lathi);
    cudaGetSymbolAddress((void**)&latlo,  g_latlo);

    const size_t HP = 896 * 256;
    __nv_bfloat16* c0hi = hd + 0*HP; __nv_bfloat16* c0lo = hd + 1*HP;
    __nv_bfloat16* c1hi = hd + 2*HP; __nv_bfloat16* c1lo = hd + 3*HP;
    __nv_bfloat16* b0hi = hd + 4*HP; __nv_bfloat16* b0lo = hd + 5*HP;
    __nv_bfloat16* b1hi = hd + 6*HP; __nv_bfloat16* b1lo = hd + 7*HP;

    cudaFuncSetAttribute(tc_gemm,  cudaFuncAttributeMaxDynamicSharedMemorySize, SMEM_TOTAL);
    cudaFuncSetAttribute(lat_gemm, cudaFuncAttributeMaxDynamicSharedMemorySize, SMEM_TOTAL);

    // 0) weight prep
    prep_all<<<4864, 256>>>(loc_Ws, cls_Ws, box_Ws, whi, wlo,
                            lat_w3, lat_w4, lat_w5, lathi, latlo);

    // 1) laterals (672 CTAs, M=64, 2 CTAs/SM)
    {
        LatArgs L;
        L.x3 = x3; L.x4 = x4; L.x5 = x5;
        L.Whi = lathi; L.Wlo = latlo;
        L.bn_g = bn_g; L.bn_b = bn_b; L.bn_m = bn_m; L.bn_v = bn_v;
        L.Yhi = flathi; L.Ylo = flatlo;
        lat_gemm<<<672, 256, SMEM_TOTAL>>>(L);
    }

    GArgs a; memset(&a, 0, sizeof(a));
    a.split = 1 << 30;

    // 2) loc MLP: 4 layers (672 CTAs each), layer 4 fused with final dot -> logits
    {
        const __nv_bfloat16* curhi = flathi;
        const __nv_bfloat16* curlo = flatlo;
        __nv_bfloat16* phi[2] = { p0hi, p1hi };
        __nv_bfloat16* plo[2] = { p0lo, p1lo };
        for (int i = 0; i < 4; i++) {
            GArgs L = a; L.mode = 0; L.Kdim = 256; L.nrows = TOT;
            L.Ahi = curhi; L.Alo = curlo;
            L.Whi = whi + (size_t)i*65536; L.Wlo = wlo + (size_t)i*65536;
            L.pb = loc_bs + i*C; L.pg = loc_lng + i*C; L.po = loc_lnb + i*C;
            if (i == 3) { L.wf = loc_Wf; L.wfb = loc_bf; L.logits = logits; }
            else { L.Yhi = phi[i & 1]; L.Ylo = plo[i & 1]; }
            tc_gemm<<<TOT/64, 256, SMEM_TOTAL>>>(L);
            curhi = phi[i & 1]; curlo = plo[i & 1];
        }
    }

    // 3) top-k
    topk_kernel<<<BATCH, 512>>>(logits, vals, idxp);

    // 4) heads: 4 combined cls+box layers (grid 26, split 13); layer 1 = fused gather
    {
        const __nv_bfloat16 *cAhi = flathi, *cAlo = flatlo, *bAhi = flathi, *bAlo = flatlo;
        __nv_bfloat16 *cY[2][2] = { {c0hi, c0lo}, {c1hi, c1lo} };
        __nv_bfloat16 *bY[2][2] = { {b0hi, b0lo}, {b1hi, b1lo} };
        for (int i = 0; i < 4; i++) {
            GArgs L = a; L.mode = (i == 0) ? 2 : 0; L.Kdim = 256; L.nrows = 800; L.split = 13;
            L.idx = idxp;
            L.Ahi = cAhi;  L.Alo = cAlo;
            L.A2hi = bAhi; L.A2lo = bAlo;
            L.Whi  = whi + (size_t)(4+i)*65536; L.Wlo  = wlo + (size_t)(4+i)*65536;
            L.W2hi = whi + (size_t)(8+i)*65536; L.W2lo = wlo + (size_t)(8+i)*65536;
            L.pb = cls_bs + i*C;  L.pg = cls_lng + i*C;  L.po = cls_lnb + i*C;
            L.pb2 = box_bs + i*C; L.pg2 = box_lng + i*C; L.po2 = box_lnb + i*C;
            L.Yhi = cY[i & 1][0];  L.Ylo = cY[i & 1][1];
            L.Y2hi = bY[i & 1][0]; L.Y2lo = bY[i & 1][1];
            tc_gemm<<<26, 256, SMEM_TOTAL>>>(L);
            cAhi = cY[i & 1][0]; cAlo = cY[i & 1][1];
            bAhi = bY[i & 1][0]; bAlo = bY[i & 1][1];
        }
    }

    // 5) finals + scores
    finals_kernel<<<800, 128>>>(c1hi, c1lo, b1hi, b1lo,
        cls_Wf, cls_bf, box_Wf, box_bf, idxp, p_fh, p_fw, out);
    scores_kernel<<<1, 800>>>(vals, out);
}